// round 8
// baseline (speedup 1.0000x reference)
#include <cuda_runtime.h>
#include <cuda_fp16.h>

#define NN 100000
#define NE 1600000
#define NGR 16
#define DD 64
#define SCAN_CH 500
#define SCAN_NB 200   // 200 * 500 = 100000

// ---------------- scratch (static device arrays; no allocation) ----------------
__device__ int    g_deg[NN];
__device__ int    g_cur[NN];
__device__ int    g_rowptr[NN + 1];
__device__ float  g_dinv[NN];
__device__ int    g_srcs[NE];
__device__ __half g_h16a[NN * DD];   // transform outputs (dinv folded), gathered
__device__ __half g_h16b[NN * DD];   // agg1 activations (layer-2 transform input)
__device__ float  g_buf1[NN * DD];   // agg2 output (fp32, pooled)
__device__ double g_pool[NGR * DD];
__device__ int    g_pcnt[NGR];
__device__ int    g_bsum[256];
__device__ int    g_is64;
__device__ int    g_bar;             // grid barrier counter

// ---------------- packed f32x2 helpers (sm_100+) --------------------------------
__device__ __forceinline__ unsigned long long f2pack(float x, float y) {
    unsigned long long r;
    asm("mov.b64 %0, {%1, %2};" : "=l"(r) : "f"(x), "f"(y));
    return r;
}
__device__ __forceinline__ void f2unpack(unsigned long long v, float& x, float& y) {
    asm("mov.b64 {%0, %1}, %2;" : "=f"(x), "=f"(y) : "l"(v));
}
__device__ __forceinline__ unsigned long long ffma2(unsigned long long a,
                                                    unsigned long long b,
                                                    unsigned long long c) {
    unsigned long long d;
    asm("fma.rn.f32x2 %0, %1, %2, %3;" : "=l"(d) : "l"(a), "l"(b), "l"(c));
    return d;
}

__device__ __forceinline__ int load_idx(const void* p, long long i, int is64) {
    return is64 ? (int)((const long long*)p)[i] : ((const int*)p)[i];
}

// ---------------- software grid barrier (residency verified by host occupancy
// query; spin is bounded so a residency bug degrades to wrong-answer, not hang) --
__device__ __forceinline__ void gsync(int gen) {
    __syncthreads();
    if (threadIdx.x == 0) {
        __threadfence();
        atomicAdd(&g_bar, 1);
        int target = gen * (int)gridDim.x;
        unsigned long long spins = 0;
        while (atomicAdd(&g_bar, 0) < target) {
            __nanosleep(64);
            if (++spins > 100000000ULL) break;  // watchdog: never hang the GPU
        }
        __threadfence();
    }
    __syncthreads();
}

// ---------------- dense transform stage ------------------------------------------
// out[i,:] = fp16( (in[i,:] @ W) * dinv[i] ).  8 warps: warps (r, r+4) cover row r
// of a 4-row chunk; each thread caches one W column as 32 packed f32x2 regs.
template <typename Tin>
__device__ __forceinline__ void transform_stage(const Tin* __restrict__ in,
                                                const float* __restrict__ W,
                                                __half* __restrict__ out,
                                                float (*xs)[DD], float* sdv) {
    int warp = threadIdx.x >> 5;
    int lane = threadIdx.x & 31;
    int r = warp & 3;
    int col = ((warp >> 2) << 5) + lane;  // 0..63
    unsigned long long w2[DD / 2];
#pragma unroll
    for (int k = 0; k < DD / 2; k++)
        w2[k] = f2pack(W[(2 * k) * DD + col], W[(2 * k + 1) * DD + col]);

    for (int row0 = blockIdx.x * 4; row0 < NN; row0 += gridDim.x * 4) {
        int t = threadIdx.x;
        int rr = row0 + (t >> 6);
        if (rr < NN) xs[t >> 6][t & 63] = (float)in[rr * DD + (t & 63)];
        if (t < 4 && row0 + t < NN) sdv[t] = g_dinv[row0 + t];
        __syncthreads();
        int row = row0 + r;
        if (row < NN) {
            const float4* xr = (const float4*)xs[r];
            unsigned long long acc0 = f2pack(0.f, 0.f);
            unsigned long long acc1 = f2pack(0.f, 0.f);
#pragma unroll
            for (int q = 0; q < DD / 4; q++) {
                float4 xv = xr[q];
                acc0 = ffma2(f2pack(xv.x, xv.y), w2[2 * q + 0], acc0);
                acc1 = ffma2(f2pack(xv.z, xv.w), w2[2 * q + 1], acc1);
            }
            float a, b, c, d;
            f2unpack(acc0, a, b);
            f2unpack(acc1, c, d);
            out[row * DD + col] = __float2half(((a + b) + (c + d)) * sdv[r]);
        }
        __syncthreads();
    }
}

// ---------------- aggregation stage: warp per dst node ---------------------------
template <int RELU, int OUT16>
__device__ __forceinline__ void agg_stage(const __half2* __restrict__ hp,
                                          const float* __restrict__ bias,
                                          void* __restrict__ outp) {
    int gtid = blockIdx.x * blockDim.x + threadIdx.x;
    int tw = (gridDim.x * blockDim.x) >> 5;
    int lane = threadIdx.x & 31;
    float bx = bias[lane * 2 + 0];
    float by = bias[lane * 2 + 1];

    for (int node = gtid >> 5; node < NN; node += tw) {
        float2 a0 = __half22float2(hp[node * 32 + lane]);  // self-loop term
        float2 a1 = make_float2(0.f, 0.f);
        float2 a2 = make_float2(0.f, 0.f);
        float2 a3 = make_float2(0.f, 0.f);
        int beg = g_rowptr[node];
        int end = g_rowptr[node + 1];
        int i = beg;
        for (; i + 8 <= end; i += 8) {
            int s0 = g_srcs[i + 0], s1 = g_srcs[i + 1];
            int s2 = g_srcs[i + 2], s3 = g_srcs[i + 3];
            int s4 = g_srcs[i + 4], s5 = g_srcs[i + 5];
            int s6 = g_srcs[i + 6], s7 = g_srcs[i + 7];
            float2 v0 = __half22float2(hp[s0 * 32 + lane]);
            float2 v1 = __half22float2(hp[s1 * 32 + lane]);
            float2 v2 = __half22float2(hp[s2 * 32 + lane]);
            float2 v3 = __half22float2(hp[s3 * 32 + lane]);
            float2 v4 = __half22float2(hp[s4 * 32 + lane]);
            float2 v5 = __half22float2(hp[s5 * 32 + lane]);
            float2 v6 = __half22float2(hp[s6 * 32 + lane]);
            float2 v7 = __half22float2(hp[s7 * 32 + lane]);
            a0.x += v0.x; a0.y += v0.y;  a1.x += v1.x; a1.y += v1.y;
            a2.x += v2.x; a2.y += v2.y;  a3.x += v3.x; a3.y += v3.y;
            a0.x += v4.x; a0.y += v4.y;  a1.x += v5.x; a1.y += v5.y;
            a2.x += v6.x; a2.y += v6.y;  a3.x += v7.x; a3.y += v7.y;
        }
        for (; i + 2 <= end; i += 2) {
            int s0 = g_srcs[i + 0], s1 = g_srcs[i + 1];
            float2 v0 = __half22float2(hp[s0 * 32 + lane]);
            float2 v1 = __half22float2(hp[s1 * 32 + lane]);
            a0.x += v0.x; a0.y += v0.y;
            a1.x += v1.x; a1.y += v1.y;
        }
        if (i < end) {
            int s = g_srcs[i];
            float2 v = __half22float2(hp[s * 32 + lane]);
            a2.x += v.x; a2.y += v.y;
        }
        float accx = (a0.x + a1.x) + (a2.x + a3.x);
        float accy = (a0.y + a1.y) + (a2.y + a3.y);

        float dv = g_dinv[node];
        float ox = fmaf(accx, dv, bx);
        float oy = fmaf(accy, dv, by);
        if (RELU) { ox = fmaxf(ox, 0.f); oy = fmaxf(oy, 0.f); }
        if (OUT16) {
            ((__half2*)outp)[node * 32 + lane] = __float22half2_rn(make_float2(ox, oy));
        } else {
            ((float2*)outp)[node * 32 + lane] = make_float2(ox, oy);
        }
    }
}

// ---------------- barrier reset (tiny kernel; replaces memsetAsync) --------------
__global__ void k_reset() { g_bar = 0; }

// ---------------- the whole pipeline in one persistent kernel --------------------
__global__ void __launch_bounds__(256, 2)
k_fused(const float* __restrict__ x, const float* __restrict__ W1,
        const float* __restrict__ b1, const float* __restrict__ W2,
        const float* __restrict__ b2, const void* __restrict__ ei,
        const void* __restrict__ batch, float* __restrict__ out) {
    __shared__ float xs[4][DD];
    __shared__ float sdv[4];
    __shared__ int sb[256];
    __shared__ int sh[256];
    __shared__ unsigned int sdet;

    int tid = threadIdx.x;
    int gtid = blockIdx.x * blockDim.x + tid;
    int nth = gridDim.x * blockDim.x;
    int gen = 0;

    // ---- stage 0: init + dtype detect ------------------------------------------
    for (int i = gtid; i < NN; i += nth) g_deg[i] = 0;
    for (int i = gtid; i < NGR * DD; i += nth) g_pool[i] = 0.0;
    if (gtid < NGR) g_pcnt[gtid] = 0;
    if (gtid == 0) g_rowptr[NN] = NE;
    if (blockIdx.x == 0) {
        // int64 values < 2^31 have zero high (odd) words; int32 data won't.
        // reads first 32 KB, in-bounds for both layouts.
        if (tid == 0) sdet = 0u;
        __syncthreads();
        const unsigned int* w = (const unsigned int*)ei;
        unsigned int o = 0u;
        for (int j = 1 + 2 * tid; j < 8192; j += 512) o |= w[j];
        atomicOr(&sdet, o);
        __syncthreads();
        if (tid == 0) g_is64 = (sdet == 0u) ? 1 : 0;
    }
    gsync(++gen);

    int is64 = g_is64;

    // ---- stage 1: degree histogram over dst ------------------------------------
    for (int e = gtid; e < NE; e += nth) {
        int d = load_idx(ei, (long long)NE + e, is64);
        atomicAdd(&g_deg[d], 1);
    }
    gsync(++gen);

    // ---- stage 2: chunk sums + dinv --------------------------------------------
    for (int b = blockIdx.x; b < SCAN_NB; b += gridDim.x) {
        int base = b * SCAN_CH;
        int s = 0;
        for (int j = tid; j < SCAN_CH; j += 256) {
            int idx = base + j;
            if (idx < NN) {
                int d = g_deg[idx];
                s += d;
                g_dinv[idx] = rsqrtf((float)(d + 1));
            }
        }
        sb[tid] = s;
        __syncthreads();
        for (int o = 128; o > 0; o >>= 1) {
            if (tid < o) sb[tid] += sb[tid + o];
            __syncthreads();
        }
        if (tid == 0) g_bsum[b] = sb[0];
        __syncthreads();
    }
    gsync(++gen);

    // ---- stage 3: row_ptr (+ seed g_cur with slot bases) ------------------------
    for (int b = blockIdx.x; b < SCAN_NB; b += gridDim.x) {
        // redundant per-block scan of the 200 chunk sums (cheap)
        int v = (tid < SCAN_NB) ? g_bsum[tid] : 0;
        sb[tid] = v;
        __syncthreads();
        for (int o = 1; o < 256; o <<= 1) {
            int xv = sb[tid];
            int yv = (tid >= o) ? sb[tid - o] : 0;
            __syncthreads();
            sb[tid] = xv + yv;
            __syncthreads();
        }
        int chunk_off = (b > 0) ? sb[b - 1] : 0;

        int base = b * SCAN_CH;
        int i0 = base + tid * 4;
        int d0 = 0, d1 = 0, d2 = 0, d3 = 0;
        if (tid < 125) {
            d0 = g_deg[i0 + 0];
            d1 = g_deg[i0 + 1];
            d2 = g_deg[i0 + 2];
            d3 = g_deg[i0 + 3];
        }
        int s = d0 + d1 + d2 + d3;
        sh[tid] = s;
        __syncthreads();
        for (int o = 1; o < 256; o <<= 1) {
            int xv = sh[tid];
            int yv = (tid >= o) ? sh[tid - o] : 0;
            __syncthreads();
            sh[tid] = xv + yv;
            __syncthreads();
        }
        int excl = sh[tid] - s + chunk_off;
        if (tid < 125) {
            g_rowptr[i0 + 0] = excl;                g_cur[i0 + 0] = excl;
            g_rowptr[i0 + 1] = excl + d0;           g_cur[i0 + 1] = excl + d0;
            g_rowptr[i0 + 2] = excl + d0 + d1;      g_cur[i0 + 2] = excl + d0 + d1;
            g_rowptr[i0 + 3] = excl + d0 + d1 + d2; g_cur[i0 + 3] = excl + d0 + d1 + d2;
        }
        __syncthreads();
    }
    gsync(++gen);

    // ---- stage 4: scatter edges into CSR slots ---------------------------------
    for (int e = gtid; e < NE; e += nth) {
        int d = load_idx(ei, (long long)NE + e, is64);
        int s = load_idx(ei, e, is64);
        int slot = atomicAdd(&g_cur[d], 1);
        g_srcs[slot] = s;
    }
    gsync(++gen);

    // ---- stage 5-8: two GCN layers ---------------------------------------------
    transform_stage<float>(x, W1, g_h16a, xs, sdv);
    gsync(++gen);
    agg_stage<1, 1>((const __half2*)g_h16a, b1, (void*)g_h16b);
    gsync(++gen);
    transform_stage<__half>(g_h16b, W2, g_h16a, xs, sdv);
    gsync(++gen);
    agg_stage<0, 0>((const __half2*)g_h16a, b2, (void*)g_buf1);
    gsync(++gen);

    // ---- stage 9: pooling (batch is sorted; warp per contiguous range) ----------
    {
        int tw = nth >> 5;
        int gw = gtid >> 5;
        int lane = tid & 31;
        int span = (NN + tw - 1) / tw;
        int n0 = gw * span;
        if (n0 < NN) {
            int n1 = n0 + span; if (n1 > NN) n1 = NN;
            const float2* hp = (const float2*)g_buf1;
            int g = load_idx(batch, n0, is64);
            float sx = 0.f, sy = 0.f;
            int cnt = 0;
            for (int n = n0; n < n1; n++) {
                int gn = load_idx(batch, n, is64);
                if (gn != g) {
                    atomicAdd(&g_pool[g * DD + lane * 2 + 0], (double)sx);
                    atomicAdd(&g_pool[g * DD + lane * 2 + 1], (double)sy);
                    if (lane == 0) atomicAdd(&g_pcnt[g], cnt);
                    sx = 0.f; sy = 0.f; cnt = 0; g = gn;
                }
                float2 v = hp[n * 32 + lane];
                sx += v.x; sy += v.y; cnt++;
            }
            atomicAdd(&g_pool[g * DD + lane * 2 + 0], (double)sx);
            atomicAdd(&g_pool[g * DD + lane * 2 + 1], (double)sy);
            if (lane == 0) atomicAdd(&g_pcnt[g], cnt);
        }
    }
    gsync(++gen);

    // ---- stage 10: finalize -----------------------------------------------------
    if (gtid < NGR * DD) {
        int g = gtid >> 6;
        int c = g_pcnt[g];
        double denom = (double)(c > 1 ? c : 1);
        out[gtid] = (float)(g_pool[gtid] / denom);
    }
}

// ---------------- launch ----------------
extern "C" void kernel_launch(void* const* d_in, const int* in_sizes, int n_in,
                              void* d_out, int out_size) {
    const float* x  = (const float*)d_in[0];
    const float* W1 = (const float*)d_in[1];
    const float* b1 = (const float*)d_in[2];
    const float* W2 = (const float*)d_in[3];
    const float* b2 = (const float*)d_in[4];
    const void*  ei = d_in[5];      // (2, NE) row-major, int32 OR int64 (detected)
    const void*  batch = d_in[6];
    float* out = (float*)d_out;

    // residency-verified grid: the barrier is safe only if every block is
    // resident in wave 1, so size the grid from the occupancy API (pure query,
    // capture-safe), clamped to [1,2] blocks/SM.
    int dev = 0, sms = 148;
    cudaGetDevice(&dev);
    cudaDeviceGetAttribute(&sms, cudaDevAttrMultiProcessorCount, dev);
    int occ = 1;
    cudaOccupancyMaxActiveBlocksPerMultiprocessor(&occ, k_fused, 256, 0);
    if (occ < 1) occ = 1;
    if (occ > 2) occ = 2;
    int blocks = occ * sms;

    k_reset<<<1, 1>>>();
    k_fused<<<blocks, 256>>>(x, W1, b1, W2, b2, ei, batch, out);
}

// round 10
// speedup vs baseline: 1.2606x; 1.2606x over previous
#include <cuda_runtime.h>
#include <cuda_fp16.h>

#define NN 100000
#define NE 1600000
#define NGR 16
#define DD 64
#define SCAN_CH 500
#define SCAN_NB 200   // 200 * 500 = 100000
#define TB 1184       // transform grid

// ---------------- scratch (static device arrays; no allocation) ----------------
__device__ int    g_deg[NN];
__device__ int    g_cur[NN];      // seeded with rowptr slot bases by k_rowptr
__device__ int    g_rowptr[NN + 1];
__device__ float  g_dinv[NN];
__device__ int    g_srcs[NE];
__device__ __half g_h16a[NN * DD];   // transform outputs (dinv folded), gathered
__device__ __half g_h16b[NN * DD];   // agg1 activations (layer-2 transform input)
__device__ float  g_buf1[NN * DD];   // agg2 output (fp32, pooled)
__device__ double g_pool[NGR * DD];
__device__ int    g_pcnt[NGR];
__device__ int    g_bsum[256];
__device__ int    g_is64;

// ---------------- packed f32x2 helpers (sm_100+) --------------------------------
__device__ __forceinline__ unsigned long long f2pack(float x, float y) {
    unsigned long long r;
    asm("mov.b64 %0, {%1, %2};" : "=l"(r) : "f"(x), "f"(y));
    return r;
}
__device__ __forceinline__ void f2unpack(unsigned long long v, float& x, float& y) {
    asm("mov.b64 {%0, %1}, %2;" : "=f"(x), "=f"(y) : "l"(v));
}
__device__ __forceinline__ unsigned long long ffma2(unsigned long long a,
                                                    unsigned long long b,
                                                    unsigned long long c) {
    unsigned long long d;
    asm("fma.rn.f32x2 %0, %1, %2, %3;" : "=l"(d) : "l"(a), "l"(b), "l"(c));
    return d;
}

__device__ __forceinline__ int load_idx(const void* p, long long i, int is64) {
    return is64 ? (int)((const long long*)p)[i] : ((const int*)p)[i];
}

// ---------------- launch 0: dtype detect + init ----------------------------------
// int64 values < 2^31 have zero high (odd) words; int32 index data won't.
// Reads first 32 KB of edge_index, in-bounds for both layouts.
__global__ void k_detect_init(const unsigned int* __restrict__ w) {
    int i = blockIdx.x * blockDim.x + threadIdx.x;
    if (i < NN) g_deg[i] = 0;
    if (i < NGR * DD) g_pool[i] = 0.0;
    if (i < NGR) g_pcnt[i] = 0;
    if (i == 0) g_rowptr[NN] = NE;
    if (blockIdx.x == 0) {
        __shared__ unsigned int s;
        if (threadIdx.x == 0) s = 0u;
        __syncthreads();
        unsigned int o = 0u;
        for (int j = 1 + 2 * threadIdx.x; j < 8192; j += 2 * blockDim.x) o |= w[j];
        atomicOr(&s, o);
        __syncthreads();
        if (threadIdx.x == 0) g_is64 = (s == 0u) ? 1 : 0;
    }
}

// ---------------- launch 1: degree histogram over dst ----------------------------
__global__ void k_hist(const void* __restrict__ ei) {
    int e = blockIdx.x * blockDim.x + threadIdx.x;
    if (e < NE) {
        int d = load_idx(ei, (long long)NE + e, g_is64);
        atomicAdd(&g_deg[d], 1);
    }
}

// ---------------- launch 2: per-chunk sums + dinv --------------------------------
__global__ void k_bsum_dinv() {
    __shared__ int ssum[256];
    int b = blockIdx.x;
    int base = b * SCAN_CH;
    int s = 0;
    for (int j = threadIdx.x; j < SCAN_CH; j += 256) {
        int idx = base + j;
        if (idx < NN) {
            int d = g_deg[idx];
            s += d;
            g_dinv[idx] = rsqrtf((float)(d + 1));
        }
    }
    ssum[threadIdx.x] = s;
    __syncthreads();
    for (int o = 128; o > 0; o >>= 1) {
        if (threadIdx.x < o) ssum[threadIdx.x] += ssum[threadIdx.x + o];
        __syncthreads();
    }
    if (threadIdx.x == 0) g_bsum[b] = ssum[0];
}

// ---------------- transform body: out[i,:] = fp16( (in[i,:] @ W) * dinv[i] ) -----
// 8 warps: warps (r, r+4) cover row r of a 4-row chunk; each thread caches one
// W column as 32 packed f32x2 regs; x row broadcast from shared.
template <typename Tin>
__global__ void __launch_bounds__(256) k_transform(const Tin* __restrict__ in,
                                                   const float* __restrict__ W,
                                                   __half* __restrict__ out) {
    __shared__ float xs[4][DD];
    __shared__ float sdv[4];
    int warp = threadIdx.x >> 5;
    int lane = threadIdx.x & 31;
    int r = warp & 3;
    int col = ((warp >> 2) << 5) + lane;  // 0..63
    unsigned long long w2[DD / 2];
#pragma unroll
    for (int k = 0; k < DD / 2; k++)
        w2[k] = f2pack(W[(2 * k) * DD + col], W[(2 * k + 1) * DD + col]);

    for (int row0 = blockIdx.x * 4; row0 < NN; row0 += gridDim.x * 4) {
        int t = threadIdx.x;
        int rr = row0 + (t >> 6);
        if (rr < NN) xs[t >> 6][t & 63] = (float)in[rr * DD + (t & 63)];
        if (t < 4 && row0 + t < NN) sdv[t] = g_dinv[row0 + t];
        __syncthreads();
        int row = row0 + r;
        if (row < NN) {
            const float4* xr = (const float4*)xs[r];
            unsigned long long acc0 = f2pack(0.f, 0.f);
            unsigned long long acc1 = f2pack(0.f, 0.f);
#pragma unroll
            for (int q = 0; q < DD / 4; q++) {
                float4 xv = xr[q];
                acc0 = ffma2(f2pack(xv.x, xv.y), w2[2 * q + 0], acc0);
                acc1 = ffma2(f2pack(xv.z, xv.w), w2[2 * q + 1], acc1);
            }
            float a, b, c, d;
            f2unpack(acc0, a, b);
            f2unpack(acc1, c, d);
            out[row * DD + col] = __float2half(((a + b) + (c + d)) * sdv[r]);
        }
        __syncthreads();
    }
}

// ---------------- launch 4: row_ptr (+ seed g_cur); inlines the 200-chunk scan ---
__global__ void __launch_bounds__(256) k_rowptr() {
    __shared__ int sb_[256];
    __shared__ int sh[256];
    int t = threadIdx.x, b = blockIdx.x;
    int v = (t < SCAN_NB) ? g_bsum[t] : 0;
    sb_[t] = v;
    __syncthreads();
    for (int o = 1; o < 256; o <<= 1) {
        int xv = sb_[t];
        int yv = (t >= o) ? sb_[t - o] : 0;
        __syncthreads();
        sb_[t] = xv + yv;
        __syncthreads();
    }
    int chunk_off = (b > 0) ? sb_[b - 1] : 0;

    int base = b * SCAN_CH;
    int i0 = base + t * 4;
    int d0 = 0, d1 = 0, d2 = 0, d3 = 0;
    if (t < 125) {  // 125*4 = 500
        d0 = g_deg[i0 + 0];
        d1 = g_deg[i0 + 1];
        d2 = g_deg[i0 + 2];
        d3 = g_deg[i0 + 3];
    }
    int s = d0 + d1 + d2 + d3;
    sh[t] = s;
    __syncthreads();
    for (int o = 1; o < 256; o <<= 1) {
        int xv = sh[t];
        int yv = (t >= o) ? sh[t - o] : 0;
        __syncthreads();
        sh[t] = xv + yv;
        __syncthreads();
    }
    int excl = sh[t] - s + chunk_off;
    if (t < 125) {
        g_rowptr[i0 + 0] = excl;                g_cur[i0 + 0] = excl;
        g_rowptr[i0 + 1] = excl + d0;           g_cur[i0 + 1] = excl + d0;
        g_rowptr[i0 + 2] = excl + d0 + d1;      g_cur[i0 + 2] = excl + d0 + d1;
        g_rowptr[i0 + 3] = excl + d0 + d1 + d2; g_cur[i0 + 3] = excl + d0 + d1 + d2;
    }
}

// ---------------- launch 5: scatter edges into CSR slots (single atomic) ---------
__global__ void k_scatter(const void* __restrict__ ei) {
    int e = blockIdx.x * blockDim.x + threadIdx.x;
    if (e < NE) {
        int is64 = g_is64;
        int d = load_idx(ei, (long long)NE + e, is64);
        int s = load_idx(ei, e, is64);
        int slot = atomicAdd(&g_cur[d], 1);   // g_cur pre-seeded with rowptr
        g_srcs[slot] = s;
    }
}

// ---------------- launches 6,8: aggregation, warp per dst node -------------------
// out[d,:] = act( dinv[d] * (stored[d,:] + sum_{s in in(d)} stored[s,:]) + b )
template <int RELU, int OUT16>
__global__ void __launch_bounds__(256) k_agg(const __half2* __restrict__ hp,
                                             const float* __restrict__ bias,
                                             void* __restrict__ outp) {
    int gw = (blockIdx.x * blockDim.x + threadIdx.x) >> 5;
    if (gw >= NN) return;
    int lane = threadIdx.x & 31;
    int node = gw;

    float2 a0 = __half22float2(hp[node * 32 + lane]);  // self-loop term
    float2 a1 = make_float2(0.f, 0.f);
    float2 a2 = make_float2(0.f, 0.f);
    float2 a3 = make_float2(0.f, 0.f);
    int beg = g_rowptr[node];
    int end = g_rowptr[node + 1];
    int i = beg;
    for (; i + 8 <= end; i += 8) {
        int s0 = g_srcs[i + 0], s1 = g_srcs[i + 1];
        int s2 = g_srcs[i + 2], s3 = g_srcs[i + 3];
        int s4 = g_srcs[i + 4], s5 = g_srcs[i + 5];
        int s6 = g_srcs[i + 6], s7 = g_srcs[i + 7];
        float2 v0 = __half22float2(hp[s0 * 32 + lane]);
        float2 v1 = __half22float2(hp[s1 * 32 + lane]);
        float2 v2 = __half22float2(hp[s2 * 32 + lane]);
        float2 v3 = __half22float2(hp[s3 * 32 + lane]);
        float2 v4 = __half22float2(hp[s4 * 32 + lane]);
        float2 v5 = __half22float2(hp[s5 * 32 + lane]);
        float2 v6 = __half22float2(hp[s6 * 32 + lane]);
        float2 v7 = __half22float2(hp[s7 * 32 + lane]);
        a0.x += v0.x; a0.y += v0.y;  a1.x += v1.x; a1.y += v1.y;
        a2.x += v2.x; a2.y += v2.y;  a3.x += v3.x; a3.y += v3.y;
        a0.x += v4.x; a0.y += v4.y;  a1.x += v5.x; a1.y += v5.y;
        a2.x += v6.x; a2.y += v6.y;  a3.x += v7.x; a3.y += v7.y;
    }
    for (; i + 2 <= end; i += 2) {
        int s0 = g_srcs[i + 0], s1 = g_srcs[i + 1];
        float2 v0 = __half22float2(hp[s0 * 32 + lane]);
        float2 v1 = __half22float2(hp[s1 * 32 + lane]);
        a0.x += v0.x; a0.y += v0.y;
        a1.x += v1.x; a1.y += v1.y;
    }
    if (i < end) {
        int s = g_srcs[i];
        float2 v = __half22float2(hp[s * 32 + lane]);
        a2.x += v.x; a2.y += v.y;
    }
    float accx = (a0.x + a1.x) + (a2.x + a3.x);
    float accy = (a0.y + a1.y) + (a2.y + a3.y);

    float dv = g_dinv[node];
    float ox = fmaf(accx, dv, bias[lane * 2 + 0]);
    float oy = fmaf(accy, dv, bias[lane * 2 + 1]);
    if (RELU) { ox = fmaxf(ox, 0.f); oy = fmaxf(oy, 0.f); }
    if (OUT16) {
        ((__half2*)outp)[node * 32 + lane] = __float22half2_rn(make_float2(ox, oy));
    } else {
        ((float2*)outp)[node * 32 + lane] = make_float2(ox, oy);
    }
}

// ---------------- launch 9: pooling (batch sorted; warp per contiguous range) ----
#define POOL_WARPS 800
#define POOL_SPAN 125  // 800 * 125 = 100000
__global__ void k_pool(const float* __restrict__ h,
                       const void* __restrict__ batch) {
    int gw = (blockIdx.x * blockDim.x + threadIdx.x) >> 5;
    int lane = threadIdx.x & 31;
    int n0 = gw * POOL_SPAN;
    if (n0 >= NN) return;
    int n1 = n0 + POOL_SPAN;
    if (n1 > NN) n1 = NN;
    const float2* __restrict__ hp = (const float2*)h;
    int is64 = g_is64;

    int g = load_idx(batch, n0, is64);
    float sx = 0.f, sy = 0.f;
    int cnt = 0;
    for (int n = n0; n < n1; n++) {
        int gn = load_idx(batch, n, is64);
        if (gn != g) {
            atomicAdd(&g_pool[g * DD + lane * 2 + 0], (double)sx);
            atomicAdd(&g_pool[g * DD + lane * 2 + 1], (double)sy);
            if (lane == 0) atomicAdd(&g_pcnt[g], cnt);
            sx = 0.f; sy = 0.f; cnt = 0; g = gn;
        }
        float2 v = hp[n * 32 + lane];
        sx += v.x; sy += v.y; cnt++;
    }
    atomicAdd(&g_pool[g * DD + lane * 2 + 0], (double)sx);
    atomicAdd(&g_pool[g * DD + lane * 2 + 1], (double)sy);
    if (lane == 0) atomicAdd(&g_pcnt[g], cnt);
}

// ---------------- launch 10: finalize --------------------------------------------
__global__ void k_final(float* __restrict__ out) {
    int i = blockIdx.x * blockDim.x + threadIdx.x;
    if (i < NGR * DD) {
        int g = i >> 6;
        int c = g_pcnt[g];
        double denom = (double)(c > 1 ? c : 1);
        out[i] = (float)(g_pool[i] / denom);
    }
}

// ---------------- launch ----------------
extern "C" void kernel_launch(void* const* d_in, const int* in_sizes, int n_in,
                              void* d_out, int out_size) {
    const float* x  = (const float*)d_in[0];
    const float* W1 = (const float*)d_in[1];
    const float* b1 = (const float*)d_in[2];
    const float* W2 = (const float*)d_in[3];
    const float* b2 = (const float*)d_in[4];
    const void*  ei = d_in[5];      // (2, NE) row-major, int32 OR int64 (detected)
    const void*  batch = d_in[6];
    float* out = (float*)d_out;

    __half* h16a; cudaGetSymbolAddress((void**)&h16a, g_h16a);
    __half* h16b; cudaGetSymbolAddress((void**)&h16b, g_h16b);
    float*  buf1; cudaGetSymbolAddress((void**)&buf1, g_buf1);

    k_detect_init<<<(NN + 255) / 256, 256>>>((const unsigned int*)ei);           // 0
    k_hist<<<(NE + 255) / 256, 256>>>(ei);                                       // 1
    k_bsum_dinv<<<SCAN_NB, 256>>>();                                             // 2
    k_transform<float><<<TB, 256>>>(x, W1, h16a);                                // 3 (profiled)
    k_rowptr<<<SCAN_NB, 256>>>();                                                // 4
    k_scatter<<<(NE + 255) / 256, 256>>>(ei);                                    // 5
    k_agg<1, 1><<<(NN * 32 + 255) / 256, 256>>>((const __half2*)h16a, b1, h16b); // 6
    k_transform<__half><<<TB, 256>>>(h16b, W2, h16a);                            // 7
    k_agg<0, 0><<<(NN * 32 + 255) / 256, 256>>>((const __half2*)h16a, b2, buf1); // 8
    k_pool<<<POOL_WARPS * 32 / 256, 256>>>(buf1, batch);                         // 9
    k_final<<<1, 1024>>>(out);                                                   // 10
}

// round 11
// speedup vs baseline: 1.8311x; 1.4526x over previous
#include <cuda_runtime.h>
#include <cuda_fp16.h>

#define NN 100000
#define NE 1600000
#define NGR 16
#define DD 64
#define SCAN_CH 500
#define SCAN_NB 200   // 200 * 500 = 100000

// ---------------- scratch (static device arrays; no allocation) ----------------
__device__ int    g_deg[NN];
__device__ int    g_cur[NN];      // seeded with rowptr slot bases by k_rowptr
__device__ int    g_rowptr[NN + 1];
__device__ float  g_dinv[NN];
__device__ int    g_srcs[NE];
__device__ __half g_h16a[NN * DD];   // transform outputs (dinv folded), gathered
__device__ __half g_h16b[NN * DD];   // agg1 activations (layer-2 transform input)
__device__ float  g_buf1[NN * DD];   // agg2 output (fp32, pooled)
__device__ double g_pool[NGR * DD];
__device__ int    g_pcnt[NGR];
__device__ int    g_bsum[256];
__device__ int    g_is64;

__device__ __forceinline__ int load_idx(const void* p, long long i, int is64) {
    return is64 ? (int)((const long long*)p)[i] : ((const int*)p)[i];
}

// ---------------- launch 0: dtype detect + init ----------------------------------
// int64 values < 2^31 have zero high (odd) words; int32 index data won't.
// Reads first 32 KB of edge_index, in-bounds for both layouts.
__global__ void k_detect_init(const unsigned int* __restrict__ w) {
    int i = blockIdx.x * blockDim.x + threadIdx.x;
    if (i < NN) g_deg[i] = 0;
    if (i < NGR * DD) g_pool[i] = 0.0;
    if (i < NGR) g_pcnt[i] = 0;
    if (i == 0) g_rowptr[NN] = NE;
    if (blockIdx.x == 0) {
        __shared__ unsigned int s;
        if (threadIdx.x == 0) s = 0u;
        __syncthreads();
        unsigned int o = 0u;
        for (int j = 1 + 2 * threadIdx.x; j < 8192; j += 2 * blockDim.x) o |= w[j];
        atomicOr(&s, o);
        __syncthreads();
        if (threadIdx.x == 0) g_is64 = (s == 0u) ? 1 : 0;
    }
}

// ---------------- launch 1: degree histogram over dst ----------------------------
__global__ void k_hist(const void* __restrict__ ei) {
    int e = blockIdx.x * blockDim.x + threadIdx.x;
    if (e < NE) {
        int d = load_idx(ei, (long long)NE + e, g_is64);
        atomicAdd(&g_deg[d], 1);
    }
}

// ---------------- launch 2: per-chunk sums + dinv --------------------------------
__global__ void k_bsum_dinv() {
    __shared__ int ssum[256];
    int b = blockIdx.x;
    int base = b * SCAN_CH;
    int s = 0;
    for (int j = threadIdx.x; j < SCAN_CH; j += 256) {
        int idx = base + j;
        if (idx < NN) {
            int d = g_deg[idx];
            s += d;
            g_dinv[idx] = rsqrtf((float)(d + 1));
        }
    }
    ssum[threadIdx.x] = s;
    __syncthreads();
    for (int o = 128; o > 0; o >>= 1) {
        if (threadIdx.x < o) ssum[threadIdx.x] += ssum[threadIdx.x + o];
        __syncthreads();
    }
    if (threadIdx.x == 0) g_bsum[b] = ssum[0];
}

// ---------------- tensor-core transform: out = fp16( (in @ W) * dinv ) -----------
// One 64-row x 64-col tile per block (128 threads, 4 warps, 16 rows/warp).
// W split-precision in shared: W = W_hi(fp16) + W_lo(fp16 residual) -> 2 MMAs per
// fragment recover ~22 mantissa bits on W (weight quant error doesn't average out
// in the mean-pool, activation quant does). m16n8k16 HMMA, fp32 accumulate.
__device__ __forceinline__ void mma16816(float* c, unsigned a0, unsigned a1,
                                         unsigned a2, unsigned a3,
                                         unsigned b0, unsigned b1) {
    asm volatile(
        "mma.sync.aligned.m16n8k16.row.col.f32.f16.f16.f32 "
        "{%0,%1,%2,%3}, {%4,%5,%6,%7}, {%8,%9}, {%0,%1,%2,%3};\n"
        : "+f"(c[0]), "+f"(c[1]), "+f"(c[2]), "+f"(c[3])
        : "r"(a0), "r"(a1), "r"(a2), "r"(a3), "r"(b0), "r"(b1));
}

template <typename Tin>
__global__ void __launch_bounds__(128) k_transform(const Tin* __restrict__ in,
                                                   const float* __restrict__ W,
                                                   __half* __restrict__ out) {
    __shared__ __align__(16) __half sA[64][72];    // x tile, fp16, padded
    __shared__ __align__(16) __half sWhi[64][72];  // [n][k] transposed W hi
    __shared__ __align__(16) __half sWlo[64][72];  // [n][k] transposed W lo

    int tid = threadIdx.x;

    // W -> shared (transposed, split precision); once per block
    for (int idx = tid; idx < 64 * 64; idx += 128) {
        int n = idx & 63, k = idx >> 6;
        float w = W[k * 64 + n];
        __half hi = __float2half(w);
        sWhi[n][k] = hi;
        sWlo[n][k] = __float2half(w - __half2float(hi));
    }

    // x tile -> shared fp16 (zero-pad rows >= NN)
    int row0 = blockIdx.x * 64;
    for (int idx = tid; idx < 64 * 64; idx += 128) {
        int r = idx >> 6, cc = idx & 63;
        int rr = row0 + r;
        float v = (rr < NN) ? (float)in[rr * 64 + cc] : 0.f;
        sA[r][cc] = __float2half(v);
    }
    __syncthreads();

    int warp = tid >> 5, lane = tid & 31;
    int g4 = lane >> 2;       // fragment group id (0..7)
    int q = lane & 3;
    int rbase = warp * 16;

    float c[8][4];
#pragma unroll
    for (int g = 0; g < 8; g++) {
        c[g][0] = 0.f; c[g][1] = 0.f; c[g][2] = 0.f; c[g][3] = 0.f;
    }

#pragma unroll
    for (int ks = 0; ks < 4; ks++) {
        int k0 = ks * 16;
        unsigned a0 = *(const unsigned*)&sA[rbase + g4][k0 + q * 2];
        unsigned a1 = *(const unsigned*)&sA[rbase + g4 + 8][k0 + q * 2];
        unsigned a2 = *(const unsigned*)&sA[rbase + g4][k0 + q * 2 + 8];
        unsigned a3 = *(const unsigned*)&sA[rbase + g4 + 8][k0 + q * 2 + 8];
#pragma unroll
        for (int g = 0; g < 8; g++) {
            int n = g * 8 + g4;
            unsigned bh0 = *(const unsigned*)&sWhi[n][k0 + q * 2];
            unsigned bh1 = *(const unsigned*)&sWhi[n][k0 + q * 2 + 8];
            mma16816(c[g], a0, a1, a2, a3, bh0, bh1);
            unsigned bl0 = *(const unsigned*)&sWlo[n][k0 + q * 2];
            unsigned bl1 = *(const unsigned*)&sWlo[n][k0 + q * 2 + 8];
            mma16816(c[g], a0, a1, a2, a3, bl0, bl1);
        }
    }

    // epilogue: scale by dinv[row], fp16 store
    int r0 = row0 + rbase + g4;
    int r1 = r0 + 8;
    float dv0 = (r0 < NN) ? g_dinv[r0] : 0.f;
    float dv1 = (r1 < NN) ? g_dinv[r1] : 0.f;
#pragma unroll
    for (int g = 0; g < 8; g++) {
        int col = g * 8 + q * 2;
        if (r0 < NN)
            *(__half2*)&out[r0 * 64 + col] = __floats2half2_rn(c[g][0] * dv0, c[g][1] * dv0);
        if (r1 < NN)
            *(__half2*)&out[r1 * 64 + col] = __floats2half2_rn(c[g][2] * dv1, c[g][3] * dv1);
    }
}

// ---------------- launch 4: row_ptr (+ seed g_cur); inlines the 200-chunk scan ---
__global__ void __launch_bounds__(256) k_rowptr() {
    __shared__ int sb_[256];
    __shared__ int sh[256];
    int t = threadIdx.x, b = blockIdx.x;
    int v = (t < SCAN_NB) ? g_bsum[t] : 0;
    sb_[t] = v;
    __syncthreads();
    for (int o = 1; o < 256; o <<= 1) {
        int xv = sb_[t];
        int yv = (t >= o) ? sb_[t - o] : 0;
        __syncthreads();
        sb_[t] = xv + yv;
        __syncthreads();
    }
    int chunk_off = (b > 0) ? sb_[b - 1] : 0;

    int base = b * SCAN_CH;
    int i0 = base + t * 4;
    int d0 = 0, d1 = 0, d2 = 0, d3 = 0;
    if (t < 125) {  // 125*4 = 500
        d0 = g_deg[i0 + 0];
        d1 = g_deg[i0 + 1];
        d2 = g_deg[i0 + 2];
        d3 = g_deg[i0 + 3];
    }
    int s = d0 + d1 + d2 + d3;
    sh[t] = s;
    __syncthreads();
    for (int o = 1; o < 256; o <<= 1) {
        int xv = sh[t];
        int yv = (t >= o) ? sh[t - o] : 0;
        __syncthreads();
        sh[t] = xv + yv;
        __syncthreads();
    }
    int excl = sh[t] - s + chunk_off;
    if (t < 125) {
        g_rowptr[i0 + 0] = excl;                g_cur[i0 + 0] = excl;
        g_rowptr[i0 + 1] = excl + d0;           g_cur[i0 + 1] = excl + d0;
        g_rowptr[i0 + 2] = excl + d0 + d1;      g_cur[i0 + 2] = excl + d0 + d1;
        g_rowptr[i0 + 3] = excl + d0 + d1 + d2; g_cur[i0 + 3] = excl + d0 + d1 + d2;
    }
}

// ---------------- launch 5: scatter edges into CSR slots (single atomic) ---------
__global__ void k_scatter(const void* __restrict__ ei) {
    int e = blockIdx.x * blockDim.x + threadIdx.x;
    if (e < NE) {
        int is64 = g_is64;
        int d = load_idx(ei, (long long)NE + e, is64);
        int s = load_idx(ei, e, is64);
        int slot = atomicAdd(&g_cur[d], 1);   // g_cur pre-seeded with rowptr
        g_srcs[slot] = s;
    }
}

// ---------------- launches 6,8: aggregation, warp per dst node -------------------
// out[d,:] = act( dinv[d] * (stored[d,:] + sum_{s in in(d)} stored[s,:]) + b )
template <int RELU, int OUT16>
__global__ void __launch_bounds__(256) k_agg(const __half2* __restrict__ hp,
                                             const float* __restrict__ bias,
                                             void* __restrict__ outp) {
    int gw = (blockIdx.x * blockDim.x + threadIdx.x) >> 5;
    if (gw >= NN) return;
    int lane = threadIdx.x & 31;
    int node = gw;

    float2 a0 = __half22float2(hp[node * 32 + lane]);  // self-loop term
    float2 a1 = make_float2(0.f, 0.f);
    float2 a2 = make_float2(0.f, 0.f);
    float2 a3 = make_float2(0.f, 0.f);
    int beg = g_rowptr[node];
    int end = g_rowptr[node + 1];
    int i = beg;
    for (; i + 8 <= end; i += 8) {
        int s0 = g_srcs[i + 0], s1 = g_srcs[i + 1];
        int s2 = g_srcs[i + 2], s3 = g_srcs[i + 3];
        int s4 = g_srcs[i + 4], s5 = g_srcs[i + 5];
        int s6 = g_srcs[i + 6], s7 = g_srcs[i + 7];
        float2 v0 = __half22float2(hp[s0 * 32 + lane]);
        float2 v1 = __half22float2(hp[s1 * 32 + lane]);
        float2 v2 = __half22float2(hp[s2 * 32 + lane]);
        float2 v3 = __half22float2(hp[s3 * 32 + lane]);
        float2 v4 = __half22float2(hp[s4 * 32 + lane]);
        float2 v5 = __half22float2(hp[s5 * 32 + lane]);
        float2 v6 = __half22float2(hp[s6 * 32 + lane]);
        float2 v7 = __half22float2(hp[s7 * 32 + lane]);
        a0.x += v0.x; a0.y += v0.y;  a1.x += v1.x; a1.y += v1.y;
        a2.x += v2.x; a2.y += v2.y;  a3.x += v3.x; a3.y += v3.y;
        a0.x += v4.x; a0.y += v4.y;  a1.x += v5.x; a1.y += v5.y;
        a2.x += v6.x; a2.y += v6.y;  a3.x += v7.x; a3.y += v7.y;
    }
    for (; i + 2 <= end; i += 2) {
        int s0 = g_srcs[i + 0], s1 = g_srcs[i + 1];
        float2 v0 = __half22float2(hp[s0 * 32 + lane]);
        float2 v1 = __half22float2(hp[s1 * 32 + lane]);
        a0.x += v0.x; a0.y += v0.y;
        a1.x += v1.x; a1.y += v1.y;
    }
    if (i < end) {
        int s = g_srcs[i];
        float2 v = __half22float2(hp[s * 32 + lane]);
        a2.x += v.x; a2.y += v.y;
    }
    float accx = (a0.x + a1.x) + (a2.x + a3.x);
    float accy = (a0.y + a1.y) + (a2.y + a3.y);

    float dv = g_dinv[node];
    float ox = fmaf(accx, dv, bias[lane * 2 + 0]);
    float oy = fmaf(accy, dv, bias[lane * 2 + 1]);
    if (RELU) { ox = fmaxf(ox, 0.f); oy = fmaxf(oy, 0.f); }
    if (OUT16) {
        ((__half2*)outp)[node * 32 + lane] = __float22half2_rn(make_float2(ox, oy));
    } else {
        ((float2*)outp)[node * 32 + lane] = make_float2(ox, oy);
    }
}

// ---------------- launch 9: pooling (batch sorted; warp per contiguous range) ----
#define POOL_WARPS 800
#define POOL_SPAN 125  // 800 * 125 = 100000
__global__ void k_pool(const float* __restrict__ h,
                       const void* __restrict__ batch) {
    int gw = (blockIdx.x * blockDim.x + threadIdx.x) >> 5;
    int lane = threadIdx.x & 31;
    int n0 = gw * POOL_SPAN;
    if (n0 >= NN) return;
    int n1 = n0 + POOL_SPAN;
    if (n1 > NN) n1 = NN;
    const float2* __restrict__ hp = (const float2*)h;
    int is64 = g_is64;

    int g = load_idx(batch, n0, is64);
    float sx = 0.f, sy = 0.f;
    int cnt = 0;
    for (int n = n0; n < n1; n++) {
        int gn = load_idx(batch, n, is64);
        if (gn != g) {
            atomicAdd(&g_pool[g * DD + lane * 2 + 0], (double)sx);
            atomicAdd(&g_pool[g * DD + lane * 2 + 1], (double)sy);
            if (lane == 0) atomicAdd(&g_pcnt[g], cnt);
            sx = 0.f; sy = 0.f; cnt = 0; g = gn;
        }
        float2 v = hp[n * 32 + lane];
        sx += v.x; sy += v.y; cnt++;
    }
    atomicAdd(&g_pool[g * DD + lane * 2 + 0], (double)sx);
    atomicAdd(&g_pool[g * DD + lane * 2 + 1], (double)sy);
    if (lane == 0) atomicAdd(&g_pcnt[g], cnt);
}

// ---------------- launch 10: finalize --------------------------------------------
__global__ void k_final(float* __restrict__ out) {
    int i = blockIdx.x * blockDim.x + threadIdx.x;
    if (i < NGR * DD) {
        int g = i >> 6;
        int c = g_pcnt[g];
        double denom = (double)(c > 1 ? c : 1);
        out[i] = (float)(g_pool[i] / denom);
    }
}

// ---------------- launch ----------------
extern "C" void kernel_launch(void* const* d_in, const int* in_sizes, int n_in,
                              void* d_out, int out_size) {
    const float* x  = (const float*)d_in[0];
    const float* W1 = (const float*)d_in[1];
    const float* b1 = (const float*)d_in[2];
    const float* W2 = (const float*)d_in[3];
    const float* b2 = (const float*)d_in[4];
    const void*  ei = d_in[5];      // (2, NE) row-major, int32 OR int64 (detected)
    const void*  batch = d_in[6];
    float* out = (float*)d_out;

    __half* h16a; cudaGetSymbolAddress((void**)&h16a, g_h16a);
    __half* h16b; cudaGetSymbolAddress((void**)&h16b, g_h16b);
    float*  buf1; cudaGetSymbolAddress((void**)&buf1, g_buf1);

    int tgrid = (NN + 63) / 64;  // 1563 row tiles

    k_detect_init<<<(NN + 255) / 256, 256>>>((const unsigned int*)ei);           // 0
    k_hist<<<(NE + 255) / 256, 256>>>(ei);                                       // 1
    k_bsum_dinv<<<SCAN_NB, 256>>>();                                             // 2
    k_transform<float><<<tgrid, 128>>>(x, W1, h16a);                             // 3 (profiled)
    k_rowptr<<<SCAN_NB, 256>>>();                                                // 4
    k_scatter<<<(NE + 255) / 256, 256>>>(ei);                                    // 5
    k_agg<1, 1><<<(NN * 32 + 255) / 256, 256>>>((const __half2*)h16a, b1, h16b); // 6
    k_transform<__half><<<tgrid, 128>>>(h16b, W2, h16a);                         // 7
    k_agg<0, 0><<<(NN * 32 + 255) / 256, 256>>>((const __half2*)h16a, b2, buf1); // 8
    k_pool<<<POOL_WARPS * 32 / 256, 256>>>(buf1, batch);                         // 9
    k_final<<<1, 1024>>>(out);                                                   // 10
}

// round 12
// speedup vs baseline: 1.9166x; 1.0467x over previous
#include <cuda_runtime.h>
#include <cuda_fp16.h>

#define NN 100000
#define NE 1600000
#define NGR 16
#define DD 64
#define SCAN_CH 500
#define SCAN_NB 200   // 200 * 500 = 100000
#define WUNITS (64 * 20)   // 16B units per prepped W (stride 20/row for bank-safety)

// ---------------- scratch (static device arrays; no allocation) ----------------
__device__ int    g_deg[NN];
__device__ int    g_cur[NN];      // seeded with rowptr slot bases by k_rowptr
__device__ int    g_rowptr[NN + 1];
__device__ float  g_dinv[NN];
__device__ int    g_srcs[NE];
__device__ __half g_h16a[NN * DD];   // transform outputs (dinv folded), gathered
__device__ __half g_h16b[NN * DD];   // agg1 activations (layer-2 transform input)
__device__ float  g_buf1[NN * DD];   // agg2 output (fp32, pooled)
__device__ double g_pool[NGR * DD];
__device__ int    g_pcnt[NGR];
__device__ int    g_bsum[256];
__device__ int    g_is64;
__device__ uint4  g_wfrag[2][WUNITS];  // fragment-ready split-precision W1/W2

__device__ __forceinline__ int load_idx(const void* p, long long i, int is64) {
    return is64 ? (int)((const long long*)p)[i] : ((const int*)p)[i];
}

__device__ __forceinline__ unsigned packh2(__half a, __half b) {
    __half2 t = __halves2half2(a, b);
    return *(unsigned*)&t;
}

// ---------------- launch 0: dtype detect + init + W fragment prep ----------------
// Fragment layout per W: unit(n,ks,q) = n*20 + ks*4 + q  (16B each), holding
// {hi[k0],hi[k0+1],hi[k0+8],hi[k0+9], lo[...same...]} with k0 = 16*ks + 2*q,
// where hi=fp16(W[k][n]), lo=fp16(W[k][n]-hi)  (split precision, 2 MMAs).
__global__ void k_detect_init(const unsigned int* __restrict__ w,
                              const float* __restrict__ W1,
                              const float* __restrict__ W2) {
    int i = blockIdx.x * blockDim.x + threadIdx.x;
    if (i < NN) g_deg[i] = 0;
    if (i < NGR * DD) g_pool[i] = 0.0;
    if (i < NGR) g_pcnt[i] = 0;
    if (i == 0) g_rowptr[NN] = NE;
    if (blockIdx.x == 0) {
        // int64 values < 2^31 have zero high (odd) words; int32 data won't.
        // reads first 32 KB of edge_index, in-bounds for both layouts.
        __shared__ unsigned int s;
        if (threadIdx.x == 0) s = 0u;
        __syncthreads();
        unsigned int o = 0u;
        for (int j = 1 + 2 * threadIdx.x; j < 8192; j += 2 * blockDim.x) o |= w[j];
        atomicOr(&s, o);
        __syncthreads();
        if (threadIdx.x == 0) g_is64 = (s == 0u) ? 1 : 0;
    } else if (blockIdx.x == 1 || blockIdx.x == 2) {
        const float* W = (blockIdx.x == 1) ? W1 : W2;
        uint4* dst = g_wfrag[blockIdx.x - 1];
        for (int f = threadIdx.x; f < 1024; f += blockDim.x) {
            int n = f >> 4;
            int ks = (f >> 2) & 3;
            int q = f & 3;
            int k0 = ks * 16 + q * 2;
            float w0 = W[(k0 + 0) * 64 + n];
            float w1 = W[(k0 + 1) * 64 + n];
            float w8 = W[(k0 + 8) * 64 + n];
            float w9 = W[(k0 + 9) * 64 + n];
            __half h0 = __float2half(w0), h1 = __float2half(w1);
            __half h8 = __float2half(w8), h9 = __float2half(w9);
            uint4 v;
            v.x = packh2(h0, h1);
            v.y = packh2(h8, h9);
            v.z = packh2(__float2half(w0 - __half2float(h0)),
                         __float2half(w1 - __half2float(h1)));
            v.w = packh2(__float2half(w8 - __half2float(h8)),
                         __float2half(w9 - __half2float(h9)));
            dst[n * 20 + ks * 4 + q] = v;
        }
    }
}

// ---------------- launch 1: degree histogram over dst (2 edges/thread) -----------
__global__ void k_hist(const void* __restrict__ ei) {
    int t = blockIdx.x * blockDim.x + threadIdx.x;
    if (t * 2 >= NE) return;
    if (g_is64) {
        const longlong2* d = (const longlong2*)((const long long*)ei + NE);
        longlong2 v = d[t];
        atomicAdd(&g_deg[(int)v.x], 1);
        atomicAdd(&g_deg[(int)v.y], 1);
    } else {
        const int2* d = (const int2*)((const int*)ei + NE);
        int2 v = d[t];
        atomicAdd(&g_deg[v.x], 1);
        atomicAdd(&g_deg[v.y], 1);
    }
}

// ---------------- launch 2: per-chunk sums + dinv --------------------------------
__global__ void k_bsum_dinv() {
    __shared__ int ssum[256];
    int b = blockIdx.x;
    int base = b * SCAN_CH;
    int s = 0;
    for (int j = threadIdx.x; j < SCAN_CH; j += 256) {
        int idx = base + j;
        if (idx < NN) {
            int d = g_deg[idx];
            s += d;
            g_dinv[idx] = rsqrtf((float)(d + 1));
        }
    }
    ssum[threadIdx.x] = s;
    __syncthreads();
    for (int o = 128; o > 0; o >>= 1) {
        if (threadIdx.x < o) ssum[threadIdx.x] += ssum[threadIdx.x + o];
        __syncthreads();
    }
    if (threadIdx.x == 0) g_bsum[b] = ssum[0];
}

// ---------------- tensor-core transform: out = fp16( (in @ W) * dinv ) -----------
// One 64x64 tile per block (128 threads, 4 warps). B fragments come from the
// prepped layout: one LDS.128 yields {bh0,bh1,bl0,bl1} (hi+lo split precision).
__device__ __forceinline__ void mma16816(float* c, unsigned a0, unsigned a1,
                                         unsigned a2, unsigned a3,
                                         unsigned b0, unsigned b1) {
    asm volatile(
        "mma.sync.aligned.m16n8k16.row.col.f32.f16.f16.f32 "
        "{%0,%1,%2,%3}, {%4,%5,%6,%7}, {%8,%9}, {%0,%1,%2,%3};\n"
        : "+f"(c[0]), "+f"(c[1]), "+f"(c[2]), "+f"(c[3])
        : "r"(a0), "r"(a1), "r"(a2), "r"(a3), "r"(b0), "r"(b1));
}

template <typename Tin>
__global__ void __launch_bounds__(128) k_transform(const Tin* __restrict__ in,
                                                   int widx,
                                                   __half* __restrict__ out) {
    __shared__ __align__(16) __half sA[64][72];  // x tile, fp16, padded
    __shared__ uint4 sW[WUNITS];                 // prepped W fragments

    int tid = threadIdx.x;

    // W fragments -> shared (vectorized 16B copies)
    {
        const uint4* src = g_wfrag[widx];
        for (int i = tid; i < WUNITS; i += 128) sW[i] = src[i];
    }

    // x tile -> shared fp16 (vectorized; zero-pad rows >= NN)
    int row0 = blockIdx.x * 64;
    if (sizeof(Tin) == 4) {
        const float4* xin = (const float4*)((const void*)(in + (size_t)row0 * 64));
        for (int i = tid; i < 1024; i += 128) {
            int r = i >> 4, c4 = i & 15;
            int rr = row0 + r;
            float4 v = (rr < NN) ? xin[i] : make_float4(0.f, 0.f, 0.f, 0.f);
            uint2 s2;
            s2.x = packh2(__float2half(v.x), __float2half(v.y));
            s2.y = packh2(__float2half(v.z), __float2half(v.w));
            *(uint2*)&sA[r][c4 * 4] = s2;
        }
    } else {
        const uint4* xin = (const uint4*)((const void*)(in + (size_t)row0 * 64));
        for (int i = tid; i < 512; i += 128) {
            int r = i >> 3, c8 = i & 7;
            int rr = row0 + r;
            uint4 v = (rr < NN) ? xin[i] : make_uint4(0u, 0u, 0u, 0u);
            *(uint4*)&sA[r][c8 * 8] = v;
        }
    }
    __syncthreads();

    int warp = tid >> 5, lane = tid & 31;
    int g4 = lane >> 2;  // 0..7
    int q = lane & 3;
    int rbase = warp * 16;

    float c[8][4];
#pragma unroll
    for (int g = 0; g < 8; g++) {
        c[g][0] = 0.f; c[g][1] = 0.f; c[g][2] = 0.f; c[g][3] = 0.f;
    }

#pragma unroll
    for (int ks = 0; ks < 4; ks++) {
        int k0 = ks * 16;
        unsigned a0 = *(const unsigned*)&sA[rbase + g4][k0 + q * 2];
        unsigned a1 = *(const unsigned*)&sA[rbase + g4 + 8][k0 + q * 2];
        unsigned a2 = *(const unsigned*)&sA[rbase + g4][k0 + q * 2 + 8];
        unsigned a3 = *(const unsigned*)&sA[rbase + g4 + 8][k0 + q * 2 + 8];
#pragma unroll
        for (int g = 0; g < 8; g++) {
            int n = g * 8 + g4;
            uint4 bb = sW[n * 20 + ks * 4 + q];   // {bh0,bh1,bl0,bl1}
            mma16816(c[g], a0, a1, a2, a3, bb.x, bb.y);
            mma16816(c[g], a0, a1, a2, a3, bb.z, bb.w);
        }
    }

    // epilogue: scale by dinv[row], fp16 store
    int r0 = row0 + rbase + g4;
    int r1 = r0 + 8;
    float dv0 = (r0 < NN) ? g_dinv[r0] : 0.f;
    float dv1 = (r1 < NN) ? g_dinv[r1] : 0.f;
#pragma unroll
    for (int g = 0; g < 8; g++) {
        int col = g * 8 + q * 2;
        if (r0 < NN)
            *(__half2*)&out[r0 * 64 + col] = __floats2half2_rn(c[g][0] * dv0, c[g][1] * dv0);
        if (r1 < NN)
            *(__half2*)&out[r1 * 64 + col] = __floats2half2_rn(c[g][2] * dv1, c[g][3] * dv1);
    }
}

// ---------------- launch 4: row_ptr (+ seed g_cur); inlines the 200-chunk scan ---
__global__ void __launch_bounds__(256) k_rowptr() {
    __shared__ int sb_[256];
    __shared__ int sh[256];
    int t = threadIdx.x, b = blockIdx.x;
    int v = (t < SCAN_NB) ? g_bsum[t] : 0;
    sb_[t] = v;
    __syncthreads();
    for (int o = 1; o < 256; o <<= 1) {
        int xv = sb_[t];
        int yv = (t >= o) ? sb_[t - o] : 0;
        __syncthreads();
        sb_[t] = xv + yv;
        __syncthreads();
    }
    int chunk_off = (b > 0) ? sb_[b - 1] : 0;

    int base = b * SCAN_CH;
    int i0 = base + t * 4;
    int d0 = 0, d1 = 0, d2 = 0, d3 = 0;
    if (t < 125) {  // 125*4 = 500
        d0 = g_deg[i0 + 0];
        d1 = g_deg[i0 + 1];
        d2 = g_deg[i0 + 2];
        d3 = g_deg[i0 + 3];
    }
    int s = d0 + d1 + d2 + d3;
    sh[t] = s;
    __syncthreads();
    for (int o = 1; o < 256; o <<= 1) {
        int xv = sh[t];
        int yv = (t >= o) ? sh[t - o] : 0;
        __syncthreads();
        sh[t] = xv + yv;
        __syncthreads();
    }
    int excl = sh[t] - s + chunk_off;
    if (t < 125) {
        g_rowptr[i0 + 0] = excl;                g_cur[i0 + 0] = excl;
        g_rowptr[i0 + 1] = excl + d0;           g_cur[i0 + 1] = excl + d0;
        g_rowptr[i0 + 2] = excl + d0 + d1;      g_cur[i0 + 2] = excl + d0 + d1;
        g_rowptr[i0 + 3] = excl + d0 + d1 + d2; g_cur[i0 + 3] = excl + d0 + d1 + d2;
    }
}

// ---------------- launch 5: scatter edges into CSR slots (2 edges/thread) --------
__global__ void k_scatter(const void* __restrict__ ei) {
    int t = blockIdx.x * blockDim.x + threadIdx.x;
    if (t * 2 >= NE) return;
    if (g_is64) {
        const longlong2* sp = (const longlong2*)ei;
        const longlong2* dp = (const longlong2*)((const long long*)ei + NE);
        longlong2 sv = sp[t];
        longlong2 dv = dp[t];
        int slot0 = atomicAdd(&g_cur[(int)dv.x], 1);
        g_srcs[slot0] = (int)sv.x;
        int slot1 = atomicAdd(&g_cur[(int)dv.y], 1);
        g_srcs[slot1] = (int)sv.y;
    } else {
        const int2* sp = (const int2*)ei;
        const int2* dp = (const int2*)((const int*)ei + NE);
        int2 sv = sp[t];
        int2 dv = dp[t];
        int slot0 = atomicAdd(&g_cur[dv.x], 1);
        g_srcs[slot0] = sv.x;
        int slot1 = atomicAdd(&g_cur[dv.y], 1);
        g_srcs[slot1] = sv.y;
    }
}

// ---------------- launches 6,8: aggregation, warp per dst node -------------------
// out[d,:] = act( dinv[d] * (stored[d,:] + sum_{s in in(d)} stored[s,:]) + b )
template <int RELU, int OUT16>
__global__ void __launch_bounds__(256) k_agg(const __half2* __restrict__ hp,
                                             const float* __restrict__ bias,
                                             void* __restrict__ outp) {
    int gw = (blockIdx.x * blockDim.x + threadIdx.x) >> 5;
    if (gw >= NN) return;
    int lane = threadIdx.x & 31;
    int node = gw;

    float2 a0 = __half22float2(hp[node * 32 + lane]);  // self-loop term
    float2 a1 = make_float2(0.f, 0.f);
    float2 a2 = make_float2(0.f, 0.f);
    float2 a3 = make_float2(0.f, 0.f);
    int beg = g_rowptr[node];
    int end = g_rowptr[node + 1];
    int i = beg;
    for (; i + 8 <= end; i += 8) {
        int s0 = g_srcs[i + 0], s1 = g_srcs[i + 1];
        int s2 = g_srcs[i + 2], s3 = g_srcs[i + 3];
        int s4 = g_srcs[i + 4], s5 = g_srcs[i + 5];
        int s6 = g_srcs[i + 6], s7 = g_srcs[i + 7];
        float2 v0 = __half22float2(hp[s0 * 32 + lane]);
        float2 v1 = __half22float2(hp[s1 * 32 + lane]);
        float2 v2 = __half22float2(hp[s2 * 32 + lane]);
        float2 v3 = __half22float2(hp[s3 * 32 + lane]);
        float2 v4 = __half22float2(hp[s4 * 32 + lane]);
        float2 v5 = __half22float2(hp[s5 * 32 + lane]);
        float2 v6 = __half22float2(hp[s6 * 32 + lane]);
        float2 v7 = __half22float2(hp[s7 * 32 + lane]);
        a0.x += v0.x; a0.y += v0.y;  a1.x += v1.x; a1.y += v1.y;
        a2.x += v2.x; a2.y += v2.y;  a3.x += v3.x; a3.y += v3.y;
        a0.x += v4.x; a0.y += v4.y;  a1.x += v5.x; a1.y += v5.y;
        a2.x += v6.x; a2.y += v6.y;  a3.x += v7.x; a3.y += v7.y;
    }
    for (; i + 2 <= end; i += 2) {
        int s0 = g_srcs[i + 0], s1 = g_srcs[i + 1];
        float2 v0 = __half22float2(hp[s0 * 32 + lane]);
        float2 v1 = __half22float2(hp[s1 * 32 + lane]);
        a0.x += v0.x; a0.y += v0.y;
        a1.x += v1.x; a1.y += v1.y;
    }
    if (i < end) {
        int s = g_srcs[i];
        float2 v = __half22float2(hp[s * 32 + lane]);
        a2.x += v.x; a2.y += v.y;
    }
    float accx = (a0.x + a1.x) + (a2.x + a3.x);
    float accy = (a0.y + a1.y) + (a2.y + a3.y);

    float dv = g_dinv[node];
    float ox = fmaf(accx, dv, bias[lane * 2 + 0]);
    float oy = fmaf(accy, dv, bias[lane * 2 + 1]);
    if (RELU) { ox = fmaxf(ox, 0.f); oy = fmaxf(oy, 0.f); }
    if (OUT16) {
        ((__half2*)outp)[node * 32 + lane] = __float22half2_rn(make_float2(ox, oy));
    } else {
        ((float2*)outp)[node * 32 + lane] = make_float2(ox, oy);
    }
}

// ---------------- launch 9: pooling (batch sorted; warp per contiguous range) ----
#define POOL_WARPS 800
#define POOL_SPAN 125  // 800 * 125 = 100000
__global__ void k_pool(const float* __restrict__ h,
                       const void* __restrict__ batch) {
    int gw = (blockIdx.x * blockDim.x + threadIdx.x) >> 5;
    int lane = threadIdx.x & 31;
    int n0 = gw * POOL_SPAN;
    if (n0 >= NN) return;
    int n1 = n0 + POOL_SPAN;
    if (n1 > NN) n1 = NN;
    const float2* __restrict__ hp = (const float2*)h;
    int is64 = g_is64;

    int g = load_idx(batch, n0, is64);
    float sx = 0.f, sy = 0.f;
    int cnt = 0;
    for (int n = n0; n < n1; n++) {
        int gn = load_idx(batch, n, is64);
        if (gn != g) {
            atomicAdd(&g_pool[g * DD + lane * 2 + 0], (double)sx);
            atomicAdd(&g_pool[g * DD + lane * 2 + 1], (double)sy);
            if (lane == 0) atomicAdd(&g_pcnt[g], cnt);
            sx = 0.f; sy = 0.f; cnt = 0; g = gn;
        }
        float2 v = hp[n * 32 + lane];
        sx += v.x; sy += v.y; cnt++;
    }
    atomicAdd(&g_pool[g * DD + lane * 2 + 0], (double)sx);
    atomicAdd(&g_pool[g * DD + lane * 2 + 1], (double)sy);
    if (lane == 0) atomicAdd(&g_pcnt[g], cnt);
}

// ---------------- launch 10: finalize --------------------------------------------
__global__ void k_final(float* __restrict__ out) {
    int i = blockIdx.x * blockDim.x + threadIdx.x;
    if (i < NGR * DD) {
        int g = i >> 6;
        int c = g_pcnt[g];
        double denom = (double)(c > 1 ? c : 1);
        out[i] = (float)(g_pool[i] / denom);
    }
}

// ---------------- launch ----------------
extern "C" void kernel_launch(void* const* d_in, const int* in_sizes, int n_in,
                              void* d_out, int out_size) {
    const float* x  = (const float*)d_in[0];
    const float* W1 = (const float*)d_in[1];
    const float* b1 = (const float*)d_in[2];
    const float* W2 = (const float*)d_in[3];
    const float* b2 = (const float*)d_in[4];
    const void*  ei = d_in[5];      // (2, NE) row-major, int32 OR int64 (detected)
    const void*  batch = d_in[6];
    float* out = (float*)d_out;

    __half* h16a; cudaGetSymbolAddress((void**)&h16a, g_h16a);
    __half* h16b; cudaGetSymbolAddress((void**)&h16b, g_h16b);
    float*  buf1; cudaGetSymbolAddress((void**)&buf1, g_buf1);

    int tgrid = (NN + 63) / 64;  // 1563 row tiles

    k_detect_init<<<(NN + 255) / 256, 256>>>((const unsigned int*)ei, W1, W2);   // 0
    k_hist<<<(NE / 2 + 255) / 256, 256>>>(ei);                                   // 1
    k_bsum_dinv<<<SCAN_NB, 256>>>();                                             // 2
    k_transform<float><<<tgrid, 128>>>(x, 0, h16a);                              // 3 (profiled)
    k_rowptr<<<SCAN_NB, 256>>>();                                                // 4
    k_scatter<<<(NE / 2 + 255) / 256, 256>>>(ei);                                // 5
    k_agg<1, 1><<<(NN * 32 + 255) / 256, 256>>>((const __half2*)h16a, b1, h16b); // 6
    k_transform<__half><<<tgrid, 128>>>(h16b, 1, h16a);                          // 7
    k_agg<0, 0><<<(NN * 32 + 255) / 256, 256>>>((const __half2*)h16a, b2, buf1); // 8
    k_pool<<<POOL_WARPS * 32 / 256, 256>>>(buf1, batch);                         // 9
    k_final<<<1, 1024>>>(out);                                                   // 10
}

// round 13
// speedup vs baseline: 2.0777x; 1.0841x over previous
#include <cuda_runtime.h>
#include <cuda_fp16.h>

#define NN 100000
#define NE 1600000
#define NGR 16
#define DD 64
#define SCAN_CH 500
#define SCAN_NB 200   // 200 * 500 = 100000
#define WUNITS (64 * 20)   // 16B units per prepped W (stride 20/row for bank-safety)

// ---------------- scratch (static device arrays; no allocation) ----------------
__device__ int    g_deg[NN];
__device__ int    g_cur[NN];      // seeded with rowptr slot bases by k_rowptr
__device__ int    g_rowptr[NN + 1];
__device__ float  g_dinv[NN];
__device__ int    g_srcs[NE];
__device__ __half g_h16a[NN * DD];   // transform1 outputs (dinv folded), gathered
__device__ __half g_h16b[NN * DD];   // P = dinv * relu(layer1)  (agg2 input)
__device__ float  g_buf1[NN * DD];   // z = dinv*(P_self + sum P_src)  (pooled)
__device__ double g_pool[NGR * DD];
__device__ int    g_pcnt[NGR];
__device__ int    g_bsum[256];
__device__ int    g_is64;
__device__ uint4  g_wfrag[WUNITS];   // fragment-ready split-precision W1

__device__ __forceinline__ int load_idx(const void* p, long long i, int is64) {
    return is64 ? (int)((const long long*)p)[i] : ((const int*)p)[i];
}

__device__ __forceinline__ unsigned packh2(__half a, __half b) {
    __half2 t = __halves2half2(a, b);
    return *(unsigned*)&t;
}

// ---------------- launch 0: dtype detect + init + W1 fragment prep ---------------
// Fragment layout: unit(n,ks,q) = n*20 + ks*4 + q (16B each), holding
// {hi[k0],hi[k0+1],hi[k0+8],hi[k0+9], lo[...same...]} with k0 = 16*ks + 2*q,
// where hi=fp16(W[k][n]), lo=fp16(W[k][n]-hi)  (split precision, 2 MMAs).
__global__ void k_detect_init(const unsigned int* __restrict__ w,
                              const float* __restrict__ W1) {
    int i = blockIdx.x * blockDim.x + threadIdx.x;
    if (i < NN) g_deg[i] = 0;
    if (i < NGR * DD) g_pool[i] = 0.0;
    if (i < NGR) g_pcnt[i] = 0;
    if (i == 0) g_rowptr[NN] = NE;
    if (blockIdx.x == 0) {
        // int64 values < 2^31 have zero high (odd) words; int32 data won't.
        // reads first 32 KB of edge_index, in-bounds for both layouts.
        __shared__ unsigned int s;
        if (threadIdx.x == 0) s = 0u;
        __syncthreads();
        unsigned int o = 0u;
        for (int j = 1 + 2 * threadIdx.x; j < 8192; j += 2 * blockDim.x) o |= w[j];
        atomicOr(&s, o);
        __syncthreads();
        if (threadIdx.x == 0) g_is64 = (s == 0u) ? 1 : 0;
    } else if (blockIdx.x == 1) {
        for (int f = threadIdx.x; f < 1024; f += blockDim.x) {
            int n = f >> 4;
            int ks = (f >> 2) & 3;
            int q = f & 3;
            int k0 = ks * 16 + q * 2;
            float w0 = W1[(k0 + 0) * 64 + n];
            float w1 = W1[(k0 + 1) * 64 + n];
            float w8 = W1[(k0 + 8) * 64 + n];
            float w9 = W1[(k0 + 9) * 64 + n];
            __half h0 = __float2half(w0), h1 = __float2half(w1);
            __half h8 = __float2half(w8), h9 = __float2half(w9);
            uint4 v;
            v.x = packh2(h0, h1);
            v.y = packh2(h8, h9);
            v.z = packh2(__float2half(w0 - __half2float(h0)),
                         __float2half(w1 - __half2float(h1)));
            v.w = packh2(__float2half(w8 - __half2float(h8)),
                         __float2half(w9 - __half2float(h9)));
            g_wfrag[n * 20 + ks * 4 + q] = v;
        }
    }
}

// ---------------- launch 1: degree histogram over dst (2 edges/thread) -----------
__global__ void k_hist(const void* __restrict__ ei) {
    int t = blockIdx.x * blockDim.x + threadIdx.x;
    if (t * 2 >= NE) return;
    if (g_is64) {
        const longlong2* d = (const longlong2*)((const long long*)ei + NE);
        longlong2 v = d[t];
        atomicAdd(&g_deg[(int)v.x], 1);
        atomicAdd(&g_deg[(int)v.y], 1);
    } else {
        const int2* d = (const int2*)((const int*)ei + NE);
        int2 v = d[t];
        atomicAdd(&g_deg[v.x], 1);
        atomicAdd(&g_deg[v.y], 1);
    }
}

// ---------------- launch 2: per-chunk sums + dinv --------------------------------
__global__ void k_bsum_dinv() {
    __shared__ int ssum[256];
    int b = blockIdx.x;
    int base = b * SCAN_CH;
    int s = 0;
    for (int j = threadIdx.x; j < SCAN_CH; j += 256) {
        int idx = base + j;
        if (idx < NN) {
            int d = g_deg[idx];
            s += d;
            g_dinv[idx] = rsqrtf((float)(d + 1));
        }
    }
    ssum[threadIdx.x] = s;
    __syncthreads();
    for (int o = 128; o > 0; o >>= 1) {
        if (threadIdx.x < o) ssum[threadIdx.x] += ssum[threadIdx.x + o];
        __syncthreads();
    }
    if (threadIdx.x == 0) g_bsum[b] = ssum[0];
}

// ---------------- launch 3: tensor-core transform1 -------------------------------
// out = fp16( (in @ W1) * dinv ). 128x64 tile per block (256 thr, 8 warps).
// B fragments via one LDS.128 = {bh0,bh1,bl0,bl1} (hi+lo split precision).
__device__ __forceinline__ void mma16816(float* c, unsigned a0, unsigned a1,
                                         unsigned a2, unsigned a3,
                                         unsigned b0, unsigned b1) {
    asm volatile(
        "mma.sync.aligned.m16n8k16.row.col.f32.f16.f16.f32 "
        "{%0,%1,%2,%3}, {%4,%5,%6,%7}, {%8,%9}, {%0,%1,%2,%3};\n"
        : "+f"(c[0]), "+f"(c[1]), "+f"(c[2]), "+f"(c[3])
        : "r"(a0), "r"(a1), "r"(a2), "r"(a3), "r"(b0), "r"(b1));
}

__global__ void __launch_bounds__(256) k_transform(const float* __restrict__ in,
                                                   __half* __restrict__ out) {
    __shared__ __align__(16) __half sA[128][72];  // x tile, fp16, padded
    __shared__ uint4 sW[WUNITS];                  // prepped W fragments

    int tid = threadIdx.x;

    // W fragments -> shared (vectorized 16B copies)
    for (int i = tid; i < WUNITS; i += 256) sW[i] = g_wfrag[i];

    // x tile -> shared fp16 (vectorized; zero-pad rows >= NN)
    int row0 = blockIdx.x * 128;
    {
        const float4* xin = (const float4*)((const void*)(in + (size_t)row0 * 64));
        for (int i = tid; i < 2048; i += 256) {
            int r = i >> 4, c4 = i & 15;
            int rr = row0 + r;
            float4 v = (rr < NN) ? xin[i] : make_float4(0.f, 0.f, 0.f, 0.f);
            uint2 s2;
            s2.x = packh2(__float2half(v.x), __float2half(v.y));
            s2.y = packh2(__float2half(v.z), __float2half(v.w));
            *(uint2*)&sA[r][c4 * 4] = s2;
        }
    }
    __syncthreads();

    int warp = tid >> 5, lane = tid & 31;
    int g4 = lane >> 2;  // 0..7
    int q = lane & 3;
    int rbase = warp * 16;

    float c[8][4];
#pragma unroll
    for (int g = 0; g < 8; g++) {
        c[g][0] = 0.f; c[g][1] = 0.f; c[g][2] = 0.f; c[g][3] = 0.f;
    }

#pragma unroll
    for (int ks = 0; ks < 4; ks++) {
        int k0 = ks * 16;
        unsigned a0 = *(const unsigned*)&sA[rbase + g4][k0 + q * 2];
        unsigned a1 = *(const unsigned*)&sA[rbase + g4 + 8][k0 + q * 2];
        unsigned a2 = *(const unsigned*)&sA[rbase + g4][k0 + q * 2 + 8];
        unsigned a3 = *(const unsigned*)&sA[rbase + g4 + 8][k0 + q * 2 + 8];
#pragma unroll
        for (int g = 0; g < 8; g++) {
            int n = g * 8 + g4;
            uint4 bb = sW[n * 20 + ks * 4 + q];   // {bh0,bh1,bl0,bl1}
            mma16816(c[g], a0, a1, a2, a3, bb.x, bb.y);
            mma16816(c[g], a0, a1, a2, a3, bb.z, bb.w);
        }
    }

    // epilogue: scale by dinv[row], fp16 store
    int r0 = row0 + rbase + g4;
    int r1 = r0 + 8;
    float dv0 = (r0 < NN) ? g_dinv[r0] : 0.f;
    float dv1 = (r1 < NN) ? g_dinv[r1] : 0.f;
#pragma unroll
    for (int g = 0; g < 8; g++) {
        int col = g * 8 + q * 2;
        if (r0 < NN)
            *(__half2*)&out[r0 * 64 + col] = __floats2half2_rn(c[g][0] * dv0, c[g][1] * dv0);
        if (r1 < NN)
            *(__half2*)&out[r1 * 64 + col] = __floats2half2_rn(c[g][2] * dv1, c[g][3] * dv1);
    }
}

// ---------------- launch 4: row_ptr (+ seed g_cur); inlines the 200-chunk scan ---
__global__ void __launch_bounds__(256) k_rowptr() {
    __shared__ int sb_[256];
    __shared__ int sh[256];
    int t = threadIdx.x, b = blockIdx.x;
    int v = (t < SCAN_NB) ? g_bsum[t] : 0;
    sb_[t] = v;
    __syncthreads();
    for (int o = 1; o < 256; o <<= 1) {
        int xv = sb_[t];
        int yv = (t >= o) ? sb_[t - o] : 0;
        __syncthreads();
        sb_[t] = xv + yv;
        __syncthreads();
    }
    int chunk_off = (b > 0) ? sb_[b - 1] : 0;

    int base = b * SCAN_CH;
    int i0 = base + t * 4;
    int d0 = 0, d1 = 0, d2 = 0, d3 = 0;
    if (t < 125) {  // 125*4 = 500
        d0 = g_deg[i0 + 0];
        d1 = g_deg[i0 + 1];
        d2 = g_deg[i0 + 2];
        d3 = g_deg[i0 + 3];
    }
    int s = d0 + d1 + d2 + d3;
    sh[t] = s;
    __syncthreads();
    for (int o = 1; o < 256; o <<= 1) {
        int xv = sh[t];
        int yv = (t >= o) ? sh[t - o] : 0;
        __syncthreads();
        sh[t] = xv + yv;
        __syncthreads();
    }
    int excl = sh[t] - s + chunk_off;
    if (t < 125) {
        g_rowptr[i0 + 0] = excl;                g_cur[i0 + 0] = excl;
        g_rowptr[i0 + 1] = excl + d0;           g_cur[i0 + 1] = excl + d0;
        g_rowptr[i0 + 2] = excl + d0 + d1;      g_cur[i0 + 2] = excl + d0 + d1;
        g_rowptr[i0 + 3] = excl + d0 + d1 + d2; g_cur[i0 + 3] = excl + d0 + d1 + d2;
    }
}

// ---------------- launch 5: scatter edges into CSR slots (2 edges/thread) --------
__global__ void k_scatter(const void* __restrict__ ei) {
    int t = blockIdx.x * blockDim.x + threadIdx.x;
    if (t * 2 >= NE) return;
    if (g_is64) {
        const longlong2* sp = (const longlong2*)ei;
        const longlong2* dp = (const longlong2*)((const long long*)ei + NE);
        longlong2 sv = sp[t];
        longlong2 dv = dp[t];
        int slot0 = atomicAdd(&g_cur[(int)dv.x], 1);
        g_srcs[slot0] = (int)sv.x;
        int slot1 = atomicAdd(&g_cur[(int)dv.y], 1);
        g_srcs[slot1] = (int)sv.y;
    } else {
        const int2* sp = (const int2*)ei;
        const int2* dp = (const int2*)((const int*)ei + NE);
        int2 sv = sp[t];
        int2 dv = dp[t];
        int slot0 = atomicAdd(&g_cur[dv.x], 1);
        g_srcs[slot0] = sv.x;
        int slot1 = atomicAdd(&g_cur[dv.y], 1);
        g_srcs[slot1] = sv.y;
    }
}

// ---------------- launches 6,7: aggregation, warp per dst node -------------------
// acc = stored[d,:] + sum_{s in in(d)} stored[s,:]
// agg1 (RELU,BIAS,FOLD,OUT16): P_d = dinv_d * relu(dinv_d*acc + b1)  -> fp16
// agg2 (plain):                z_d = dinv_d * acc                    -> fp32
template <int RELU, int OUT16, int FOLD, int BIAS>
__global__ void __launch_bounds__(256) k_agg(const __half2* __restrict__ hp,
                                             const float* __restrict__ bias,
                                             void* __restrict__ outp) {
    int gw = (blockIdx.x * blockDim.x + threadIdx.x) >> 5;
    if (gw >= NN) return;
    int lane = threadIdx.x & 31;
    int node = gw;

    float2 a0 = __half22float2(hp[node * 32 + lane]);  // self-loop term
    float2 a1 = make_float2(0.f, 0.f);
    float2 a2 = make_float2(0.f, 0.f);
    float2 a3 = make_float2(0.f, 0.f);
    int beg = g_rowptr[node];
    int end = g_rowptr[node + 1];
    int i = beg;
    for (; i + 8 <= end; i += 8) {
        int s0 = g_srcs[i + 0], s1 = g_srcs[i + 1];
        int s2 = g_srcs[i + 2], s3 = g_srcs[i + 3];
        int s4 = g_srcs[i + 4], s5 = g_srcs[i + 5];
        int s6 = g_srcs[i + 6], s7 = g_srcs[i + 7];
        float2 v0 = __half22float2(hp[s0 * 32 + lane]);
        float2 v1 = __half22float2(hp[s1 * 32 + lane]);
        float2 v2 = __half22float2(hp[s2 * 32 + lane]);
        float2 v3 = __half22float2(hp[s3 * 32 + lane]);
        float2 v4 = __half22float2(hp[s4 * 32 + lane]);
        float2 v5 = __half22float2(hp[s5 * 32 + lane]);
        float2 v6 = __half22float2(hp[s6 * 32 + lane]);
        float2 v7 = __half22float2(hp[s7 * 32 + lane]);
        a0.x += v0.x; a0.y += v0.y;  a1.x += v1.x; a1.y += v1.y;
        a2.x += v2.x; a2.y += v2.y;  a3.x += v3.x; a3.y += v3.y;
        a0.x += v4.x; a0.y += v4.y;  a1.x += v5.x; a1.y += v5.y;
        a2.x += v6.x; a2.y += v6.y;  a3.x += v7.x; a3.y += v7.y;
    }
    for (; i + 2 <= end; i += 2) {
        int s0 = g_srcs[i + 0], s1 = g_srcs[i + 1];
        float2 v0 = __half22float2(hp[s0 * 32 + lane]);
        float2 v1 = __half22float2(hp[s1 * 32 + lane]);
        a0.x += v0.x; a0.y += v0.y;
        a1.x += v1.x; a1.y += v1.y;
    }
    if (i < end) {
        int s = g_srcs[i];
        float2 v = __half22float2(hp[s * 32 + lane]);
        a2.x += v.x; a2.y += v.y;
    }
    float accx = (a0.x + a1.x) + (a2.x + a3.x);
    float accy = (a0.y + a1.y) + (a2.y + a3.y);

    float dv = g_dinv[node];
    float ox = accx * dv;
    float oy = accy * dv;
    if (BIAS) { ox += bias[lane * 2 + 0]; oy += bias[lane * 2 + 1]; }
    if (RELU) { ox = fmaxf(ox, 0.f); oy = fmaxf(oy, 0.f); }
    if (FOLD) { ox *= dv; oy *= dv; }   // fold next layer's source scaling
    if (OUT16) {
        ((__half2*)outp)[node * 32 + lane] = __float22half2_rn(make_float2(ox, oy));
    } else {
        ((float2*)outp)[node * 32 + lane] = make_float2(ox, oy);
    }
}

// ---------------- launch 8: pooling (batch sorted; warp per contiguous range) ----
#define POOL_WARPS 800
#define POOL_SPAN 125  // 800 * 125 = 100000
__global__ void k_pool(const float* __restrict__ h,
                       const void* __restrict__ batch) {
    int gw = (blockIdx.x * blockDim.x + threadIdx.x) >> 5;
    int lane = threadIdx.x & 31;
    int n0 = gw * POOL_SPAN;
    if (n0 >= NN) return;
    int n1 = n0 + POOL_SPAN;
    if (n1 > NN) n1 = NN;
    const float2* __restrict__ hp = (const float2*)h;
    int is64 = g_is64;

    int g = load_idx(batch, n0, is64);
    float sx = 0.f, sy = 0.f;
    int cnt = 0;
    for (int n = n0; n < n1; n++) {
        int gn = load_idx(batch, n, is64);
        if (gn != g) {
            atomicAdd(&g_pool[g * DD + lane * 2 + 0], (double)sx);
            atomicAdd(&g_pool[g * DD + lane * 2 + 1], (double)sy);
            if (lane == 0) atomicAdd(&g_pcnt[g], cnt);
            sx = 0.f; sy = 0.f; cnt = 0; g = gn;
        }
        float2 v = hp[n * 32 + lane];
        sx += v.x; sy += v.y; cnt++;
    }
    atomicAdd(&g_pool[g * DD + lane * 2 + 0], (double)sx);
    atomicAdd(&g_pool[g * DD + lane * 2 + 1], (double)sy);
    if (lane == 0) atomicAdd(&g_pcnt[g], cnt);
}

// ---------------- launch 9: finalize = (pooled mean) @ W2 + b2  (fp32) -----------
__global__ void k_final(const float* __restrict__ W2,
                        const float* __restrict__ b2,
                        float* __restrict__ out) {
    __shared__ float sm[NGR][DD];
    int t = threadIdx.x;            // 1024 = 16*64
    int g = t >> 6, n = t & 63;
    int c = g_pcnt[g];
    double denom = (double)(c > 1 ? c : 1);
    sm[g][n] = (float)(g_pool[g * DD + n] / denom);
    __syncthreads();
    float acc = 0.f;
#pragma unroll
    for (int k = 0; k < DD; k++) acc = fmaf(sm[g][k], W2[k * DD + n], acc);
    out[t] = acc + b2[n];
}

// ---------------- launch ----------------
extern "C" void kernel_launch(void* const* d_in, const int* in_sizes, int n_in,
                              void* d_out, int out_size) {
    const float* x  = (const float*)d_in[0];
    const float* W1 = (const float*)d_in[1];
    const float* b1 = (const float*)d_in[2];
    const float* W2 = (const float*)d_in[3];
    const float* b2 = (const float*)d_in[4];
    const void*  ei = d_in[5];      // (2, NE) row-major, int32 OR int64 (detected)
    const void*  batch = d_in[6];
    float* out = (float*)d_out;

    __half* h16a; cudaGetSymbolAddress((void**)&h16a, g_h16a);
    __half* h16b; cudaGetSymbolAddress((void**)&h16b, g_h16b);
    float*  buf1; cudaGetSymbolAddress((void**)&buf1, g_buf1);

    int tgrid = (NN + 127) / 128;  // 782 row tiles

    k_detect_init<<<(NN + 255) / 256, 256>>>((const unsigned int*)ei, W1);       // 0
    k_hist<<<(NE / 2 + 255) / 256, 256>>>(ei);                                   // 1
    k_bsum_dinv<<<SCAN_NB, 256>>>();                                             // 2
    k_transform<<<tgrid, 256>>>(x, h16a);                                        // 3 (profiled)
    k_rowptr<<<SCAN_NB, 256>>>();                                                // 4
    k_scatter<<<(NE / 2 + 255) / 256, 256>>>(ei);                                // 5
    k_agg<1, 1, 1, 1><<<(NN * 32 + 255) / 256, 256>>>((const __half2*)h16a, b1, h16b); // 6
    k_agg<0, 0, 0, 0><<<(NN * 32 + 255) / 256, 256>>>((const __half2*)h16b, nullptr, buf1); // 7
    k_pool<<<POOL_WARPS * 32 / 256, 256>>>(buf1, batch);                         // 8
    k_final<<<1, 1024>>>(W2, b2, out);                                           // 9
}

// round 14
// speedup vs baseline: 2.1734x; 1.0461x over previous
#include <cuda_runtime.h>
#include <cuda_fp16.h>

#define NN 100000
#define NE 1600000
#define NGR 16
#define DD 64
#define SCAN_CH 500
#define SCAN_NB 200   // 200 * 500 = 100000
#define WUNITS (64 * 20)   // 16B units per prepped W (stride 20/row for bank-safety)
#define AP_SPAN 32         // nodes per warp in fused agg2+pool

// ---------------- scratch (static device arrays; no allocation) ----------------
__device__ int    g_deg[NN];
__device__ int    g_cur[NN];      // seeded with rowptr slot bases by k_rowptr
__device__ int    g_rowptr[NN + 1];
__device__ float  g_dinv[NN];
__device__ int    g_srcs[NE];
__device__ __half g_h16a[NN * DD];   // transform1 outputs (dinv folded), gathered
__device__ __half g_h16b[NN * DD];   // P = dinv * relu(layer1)  (agg2 input)
__device__ double g_pool[NGR * DD];
__device__ int    g_pcnt[NGR];
__device__ int    g_bsum[256];
__device__ int    g_is64;
__device__ uint4  g_wfrag[WUNITS];   // fragment-ready split-precision W1

__device__ __forceinline__ int load_idx(const void* p, long long i, int is64) {
    return is64 ? (int)((const long long*)p)[i] : ((const int*)p)[i];
}

__device__ __forceinline__ unsigned packh2(__half a, __half b) {
    __half2 t = __halves2half2(a, b);
    return *(unsigned*)&t;
}

// ---------------- launch 0: dtype detect + init + W1 fragment prep ---------------
// Fragment layout: unit(n,ks,q) = n*20 + ks*4 + q (16B each), holding
// {hi[k0],hi[k0+1],hi[k0+8],hi[k0+9], lo[...same...]} with k0 = 16*ks + 2*q,
// where hi=fp16(W[k][n]), lo=fp16(W[k][n]-hi)  (split precision, 2 MMAs).
__global__ void k_detect_init(const unsigned int* __restrict__ w,
                              const float* __restrict__ W1) {
    int i = blockIdx.x * blockDim.x + threadIdx.x;
    if (i < NN) g_deg[i] = 0;
    if (i < NGR * DD) g_pool[i] = 0.0;
    if (i < NGR) g_pcnt[i] = 0;
    if (i == 0) g_rowptr[NN] = NE;
    if (blockIdx.x == 0) {
        // int64 values < 2^31 have zero high (odd) words; int32 data won't.
        // reads first 32 KB of edge_index, in-bounds for both layouts.
        __shared__ unsigned int s;
        if (threadIdx.x == 0) s = 0u;
        __syncthreads();
        unsigned int o = 0u;
        for (int j = 1 + 2 * threadIdx.x; j < 8192; j += 2 * blockDim.x) o |= w[j];
        atomicOr(&s, o);
        __syncthreads();
        if (threadIdx.x == 0) g_is64 = (s == 0u) ? 1 : 0;
    } else if (blockIdx.x == 1) {
        for (int f = threadIdx.x; f < 1024; f += blockDim.x) {
            int n = f >> 4;
            int ks = (f >> 2) & 3;
            int q = f & 3;
            int k0 = ks * 16 + q * 2;
            float w0 = W1[(k0 + 0) * 64 + n];
            float w1 = W1[(k0 + 1) * 64 + n];
            float w8 = W1[(k0 + 8) * 64 + n];
            float w9 = W1[(k0 + 9) * 64 + n];
            __half h0 = __float2half(w0), h1 = __float2half(w1);
            __half h8 = __float2half(w8), h9 = __float2half(w9);
            uint4 v;
            v.x = packh2(h0, h1);
            v.y = packh2(h8, h9);
            v.z = packh2(__float2half(w0 - __half2float(h0)),
                         __float2half(w1 - __half2float(h1)));
            v.w = packh2(__float2half(w8 - __half2float(h8)),
                         __float2half(w9 - __half2float(h9)));
            g_wfrag[n * 20 + ks * 4 + q] = v;
        }
    }
}

// ---------------- launch 1: degree histogram over dst (2 edges/thread) -----------
__global__ void k_hist(const void* __restrict__ ei) {
    int t = blockIdx.x * blockDim.x + threadIdx.x;
    if (t * 2 >= NE) return;
    if (g_is64) {
        const longlong2* d = (const longlong2*)((const long long*)ei + NE);
        longlong2 v = d[t];
        atomicAdd(&g_deg[(int)v.x], 1);
        atomicAdd(&g_deg[(int)v.y], 1);
    } else {
        const int2* d = (const int2*)((const int*)ei + NE);
        int2 v = d[t];
        atomicAdd(&g_deg[v.x], 1);
        atomicAdd(&g_deg[v.y], 1);
    }
}

// ---------------- launch 2: per-chunk sums + dinv --------------------------------
__global__ void k_bsum_dinv() {
    __shared__ int ssum[256];
    int b = blockIdx.x;
    int base = b * SCAN_CH;
    int s = 0;
    for (int j = threadIdx.x; j < SCAN_CH; j += 256) {
        int idx = base + j;
        if (idx < NN) {
            int d = g_deg[idx];
            s += d;
            g_dinv[idx] = rsqrtf((float)(d + 1));
        }
    }
    ssum[threadIdx.x] = s;
    __syncthreads();
    for (int o = 128; o > 0; o >>= 1) {
        if (threadIdx.x < o) ssum[threadIdx.x] += ssum[threadIdx.x + o];
        __syncthreads();
    }
    if (threadIdx.x == 0) g_bsum[b] = ssum[0];
}

// ---------------- launch 3: tensor-core transform1 -------------------------------
// out = fp16( (in @ W1) * dinv ). 128x64 tile per block (256 thr, 8 warps).
// B fragments via one LDS.128 = {bh0,bh1,bl0,bl1} (hi+lo split precision).
__device__ __forceinline__ void mma16816(float* c, unsigned a0, unsigned a1,
                                         unsigned a2, unsigned a3,
                                         unsigned b0, unsigned b1) {
    asm volatile(
        "mma.sync.aligned.m16n8k16.row.col.f32.f16.f16.f32 "
        "{%0,%1,%2,%3}, {%4,%5,%6,%7}, {%8,%9}, {%0,%1,%2,%3};\n"
        : "+f"(c[0]), "+f"(c[1]), "+f"(c[2]), "+f"(c[3])
        : "r"(a0), "r"(a1), "r"(a2), "r"(a3), "r"(b0), "r"(b1));
}

__global__ void __launch_bounds__(256) k_transform(const float* __restrict__ in,
                                                   __half* __restrict__ out) {
    __shared__ __align__(16) __half sA[128][72];  // x tile, fp16, padded
    __shared__ uint4 sW[WUNITS];                  // prepped W fragments

    int tid = threadIdx.x;

    // W fragments -> shared (vectorized 16B copies)
    for (int i = tid; i < WUNITS; i += 256) sW[i] = g_wfrag[i];

    // x tile -> shared fp16 (vectorized; zero-pad rows >= NN)
    int row0 = blockIdx.x * 128;
    {
        const float4* xin = (const float4*)((const void*)(in + (size_t)row0 * 64));
        for (int i = tid; i < 2048; i += 256) {
            int r = i >> 4, c4 = i & 15;
            int rr = row0 + r;
            float4 v = (rr < NN) ? xin[i] : make_float4(0.f, 0.f, 0.f, 0.f);
            uint2 s2;
            s2.x = packh2(__float2half(v.x), __float2half(v.y));
            s2.y = packh2(__float2half(v.z), __float2half(v.w));
            *(uint2*)&sA[r][c4 * 4] = s2;
        }
    }
    __syncthreads();

    int warp = tid >> 5, lane = tid & 31;
    int g4 = lane >> 2;  // 0..7
    int q = lane & 3;
    int rbase = warp * 16;

    float c[8][4];
#pragma unroll
    for (int g = 0; g < 8; g++) {
        c[g][0] = 0.f; c[g][1] = 0.f; c[g][2] = 0.f; c[g][3] = 0.f;
    }

#pragma unroll
    for (int ks = 0; ks < 4; ks++) {
        int k0 = ks * 16;
        unsigned a0 = *(const unsigned*)&sA[rbase + g4][k0 + q * 2];
        unsigned a1 = *(const unsigned*)&sA[rbase + g4 + 8][k0 + q * 2];
        unsigned a2 = *(const unsigned*)&sA[rbase + g4][k0 + q * 2 + 8];
        unsigned a3 = *(const unsigned*)&sA[rbase + g4 + 8][k0 + q * 2 + 8];
#pragma unroll
        for (int g = 0; g < 8; g++) {
            int n = g * 8 + g4;
            uint4 bb = sW[n * 20 + ks * 4 + q];   // {bh0,bh1,bl0,bl1}
            mma16816(c[g], a0, a1, a2, a3, bb.x, bb.y);
            mma16816(c[g], a0, a1, a2, a3, bb.z, bb.w);
        }
    }

    // epilogue: scale by dinv[row], fp16 store
    int r0 = row0 + rbase + g4;
    int r1 = r0 + 8;
    float dv0 = (r0 < NN) ? g_dinv[r0] : 0.f;
    float dv1 = (r1 < NN) ? g_dinv[r1] : 0.f;
#pragma unroll
    for (int g = 0; g < 8; g++) {
        int col = g * 8 + q * 2;
        if (r0 < NN)
            *(__half2*)&out[r0 * 64 + col] = __floats2half2_rn(c[g][0] * dv0, c[g][1] * dv0);
        if (r1 < NN)
            *(__half2*)&out[r1 * 64 + col] = __floats2half2_rn(c[g][2] * dv1, c[g][3] * dv1);
    }
}

// ---------------- launch 4: row_ptr (+ seed g_cur); inlines the 200-chunk scan ---
__global__ void __launch_bounds__(256) k_rowptr() {
    __shared__ int sb_[256];
    __shared__ int sh[256];
    int t = threadIdx.x, b = blockIdx.x;
    int v = (t < SCAN_NB) ? g_bsum[t] : 0;
    sb_[t] = v;
    __syncthreads();
    for (int o = 1; o < 256; o <<= 1) {
        int xv = sb_[t];
        int yv = (t >= o) ? sb_[t - o] : 0;
        __syncthreads();
        sb_[t] = xv + yv;
        __syncthreads();
    }
    int chunk_off = (b > 0) ? sb_[b - 1] : 0;

    int base = b * SCAN_CH;
    int i0 = base + t * 4;
    int d0 = 0, d1 = 0, d2 = 0, d3 = 0;
    if (t < 125) {  // 125*4 = 500
        d0 = g_deg[i0 + 0];
        d1 = g_deg[i0 + 1];
        d2 = g_deg[i0 + 2];
        d3 = g_deg[i0 + 3];
    }
    int s = d0 + d1 + d2 + d3;
    sh[t] = s;
    __syncthreads();
    for (int o = 1; o < 256; o <<= 1) {
        int xv = sh[t];
        int yv = (t >= o) ? sh[t - o] : 0;
        __syncthreads();
        sh[t] = xv + yv;
        __syncthreads();
    }
    int excl = sh[t] - s + chunk_off;
    if (t < 125) {
        g_rowptr[i0 + 0] = excl;                g_cur[i0 + 0] = excl;
        g_rowptr[i0 + 1] = excl + d0;           g_cur[i0 + 1] = excl + d0;
        g_rowptr[i0 + 2] = excl + d0 + d1;      g_cur[i0 + 2] = excl + d0 + d1;
        g_rowptr[i0 + 3] = excl + d0 + d1 + d2; g_cur[i0 + 3] = excl + d0 + d1 + d2;
    }
}

// ---------------- launch 5: scatter edges into CSR slots (2 edges/thread) --------
__global__ void k_scatter(const void* __restrict__ ei) {
    int t = blockIdx.x * blockDim.x + threadIdx.x;
    if (t * 2 >= NE) return;
    if (g_is64) {
        const longlong2* sp = (const longlong2*)ei;
        const longlong2* dp = (const longlong2*)((const long long*)ei + NE);
        longlong2 sv = sp[t];
        longlong2 dv = dp[t];
        int slot0 = atomicAdd(&g_cur[(int)dv.x], 1);
        g_srcs[slot0] = (int)sv.x;
        int slot1 = atomicAdd(&g_cur[(int)dv.y], 1);
        g_srcs[slot1] = (int)sv.y;
    } else {
        const int2* sp = (const int2*)ei;
        const int2* dp = (const int2*)((const int*)ei + NE);
        int2 sv = sp[t];
        int2 dv = dp[t];
        int slot0 = atomicAdd(&g_cur[dv.x], 1);
        g_srcs[slot0] = sv.x;
        int slot1 = atomicAdd(&g_cur[dv.y], 1);
        g_srcs[slot1] = sv.y;
    }
}

// ---------------- CSR gather for one node (warp-wide, lane = 2 feature pairs) ----
__device__ __forceinline__ float2 gather_node(const __half2* __restrict__ hp,
                                              int node, int lane) {
    float2 a0 = __half22float2(hp[node * 32 + lane]);  // self-loop term
    float2 a1 = make_float2(0.f, 0.f);
    float2 a2 = make_float2(0.f, 0.f);
    float2 a3 = make_float2(0.f, 0.f);
    int beg = g_rowptr[node];
    int end = g_rowptr[node + 1];
    int i = beg;
    for (; i + 8 <= end; i += 8) {
        int s0 = g_srcs[i + 0], s1 = g_srcs[i + 1];
        int s2 = g_srcs[i + 2], s3 = g_srcs[i + 3];
        int s4 = g_srcs[i + 4], s5 = g_srcs[i + 5];
        int s6 = g_srcs[i + 6], s7 = g_srcs[i + 7];
        float2 v0 = __half22float2(hp[s0 * 32 + lane]);
        float2 v1 = __half22float2(hp[s1 * 32 + lane]);
        float2 v2 = __half22float2(hp[s2 * 32 + lane]);
        float2 v3 = __half22float2(hp[s3 * 32 + lane]);
        float2 v4 = __half22float2(hp[s4 * 32 + lane]);
        float2 v5 = __half22float2(hp[s5 * 32 + lane]);
        float2 v6 = __half22float2(hp[s6 * 32 + lane]);
        float2 v7 = __half22float2(hp[s7 * 32 + lane]);
        a0.x += v0.x; a0.y += v0.y;  a1.x += v1.x; a1.y += v1.y;
        a2.x += v2.x; a2.y += v2.y;  a3.x += v3.x; a3.y += v3.y;
        a0.x += v4.x; a0.y += v4.y;  a1.x += v5.x; a1.y += v5.y;
        a2.x += v6.x; a2.y += v6.y;  a3.x += v7.x; a3.y += v7.y;
    }
    for (; i + 2 <= end; i += 2) {
        int s0 = g_srcs[i + 0], s1 = g_srcs[i + 1];
        float2 v0 = __half22float2(hp[s0 * 32 + lane]);
        float2 v1 = __half22float2(hp[s1 * 32 + lane]);
        a0.x += v0.x; a0.y += v0.y;
        a1.x += v1.x; a1.y += v1.y;
    }
    if (i < end) {
        int s = g_srcs[i];
        float2 v = __half22float2(hp[s * 32 + lane]);
        a2.x += v.x; a2.y += v.y;
    }
    return make_float2((a0.x + a1.x) + (a2.x + a3.x),
                       (a0.y + a1.y) + (a2.y + a3.y));
}

// ---------------- launch 6: agg1 — warp per dst node -----------------------------
// P_d = fp16( dinv_d * relu(dinv_d * acc + b1) )   (next layer's source scaling folded)
__global__ void __launch_bounds__(256) k_agg1(const __half2* __restrict__ hp,
                                              const float* __restrict__ bias,
                                              __half2* __restrict__ outp) {
    int gw = (blockIdx.x * blockDim.x + threadIdx.x) >> 5;
    if (gw >= NN) return;
    int lane = threadIdx.x & 31;
    float2 acc = gather_node(hp, gw, lane);
    float dv = g_dinv[gw];
    float ox = fmaxf(acc.x * dv + bias[lane * 2 + 0], 0.f) * dv;
    float oy = fmaxf(acc.y * dv + bias[lane * 2 + 1], 0.f) * dv;
    outp[gw * 32 + lane] = __float22half2_rn(make_float2(ox, oy));
}

// ---------------- launch 7: fused agg2 + pool ------------------------------------
// Warp handles AP_SPAN contiguous nodes (batch sorted): z_d = dinv_d * acc_d is
// accumulated into per-lane registers, flushed to g_pool on graph boundaries.
__global__ void __launch_bounds__(256) k_aggpool(const __half2* __restrict__ hp,
                                                 const void* __restrict__ batch) {
    int gw = (blockIdx.x * blockDim.x + threadIdx.x) >> 5;
    int lane = threadIdx.x & 31;
    int n0 = gw * AP_SPAN;
    if (n0 >= NN) return;
    int n1 = n0 + AP_SPAN;
    if (n1 > NN) n1 = NN;
    int is64 = g_is64;

    int g = load_idx(batch, n0, is64);
    float sx = 0.f, sy = 0.f;
    int cnt = 0;
    for (int node = n0; node < n1; node++) {
        int gn = load_idx(batch, node, is64);
        if (gn != g) {
            atomicAdd(&g_pool[g * DD + lane * 2 + 0], (double)sx);
            atomicAdd(&g_pool[g * DD + lane * 2 + 1], (double)sy);
            if (lane == 0) atomicAdd(&g_pcnt[g], cnt);
            sx = 0.f; sy = 0.f; cnt = 0; g = gn;
        }
        float2 acc = gather_node(hp, node, lane);
        float dv = g_dinv[node];
        sx += acc.x * dv;
        sy += acc.y * dv;
        cnt++;
    }
    atomicAdd(&g_pool[g * DD + lane * 2 + 0], (double)sx);
    atomicAdd(&g_pool[g * DD + lane * 2 + 1], (double)sy);
    if (lane == 0) atomicAdd(&g_pcnt[g], cnt);
}

// ---------------- launch 8: finalize = (pooled mean) @ W2 + b2  (fp32) -----------
__global__ void k_final(const float* __restrict__ W2,
                        const float* __restrict__ b2,
                        float* __restrict__ out) {
    __shared__ float sm[NGR][DD];
    int t = threadIdx.x;            // 1024 = 16*64
    int g = t >> 6, n = t & 63;
    int c = g_pcnt[g];
    double denom = (double)(c > 1 ? c : 1);
    sm[g][n] = (float)(g_pool[g * DD + n] / denom);
    __syncthreads();
    float acc = 0.f;
#pragma unroll
    for (int k = 0; k < DD; k++) acc = fmaf(sm[g][k], W2[k * DD + n], acc);
    out[t] = acc + b2[n];
}

// ---------------- launch ----------------
extern "C" void kernel_launch(void* const* d_in, const int* in_sizes, int n_in,
                              void* d_out, int out_size) {
    const float* x  = (const float*)d_in[0];
    const float* W1 = (const float*)d_in[1];
    const float* b1 = (const float*)d_in[2];
    const float* W2 = (const float*)d_in[3];
    const float* b2 = (const float*)d_in[4];
    const void*  ei = d_in[5];      // (2, NE) row-major, int32 OR int64 (detected)
    const void*  batch = d_in[6];
    float* out = (float*)d_out;

    __half* h16a; cudaGetSymbolAddress((void**)&h16a, g_h16a);
    __half* h16b; cudaGetSymbolAddress((void**)&h16b, g_h16b);

    int tgrid = (NN + 127) / 128;  // 782 row tiles
    int apwarps = (NN + AP_SPAN - 1) / AP_SPAN;  // 3125 warps

    k_detect_init<<<(NN + 255) / 256, 256>>>((const unsigned int*)ei, W1);       // 0
    k_hist<<<(NE / 2 + 255) / 256, 256>>>(ei);                                   // 1
    k_bsum_dinv<<<SCAN_NB, 256>>>();                                             // 2
    k_transform<<<tgrid, 256>>>(x, h16a);                                        // 3 (profiled)
    k_rowptr<<<SCAN_NB, 256>>>();                                                // 4
    k_scatter<<<(NE / 2 + 255) / 256, 256>>>(ei);                                // 5
    k_agg1<<<(NN * 32 + 255) / 256, 256>>>((const __half2*)h16a, b1,
                                           (__half2*)h16b);                      // 6
    k_aggpool<<<(apwarps * 32 + 255) / 256, 256>>>((const __half2*)h16b, batch); // 7
    k_final<<<1, 1024>>>(W2, b2, out);                                           // 8
}

// round 15
// speedup vs baseline: 2.2301x; 1.0261x over previous
#include <cuda_runtime.h>
#include <cuda_fp16.h>

#define NN 100000
#define NE 1600000
#define NGR 16
#define DD 64
#define SCAN_CH 500
#define SCAN_NB 200   // 200 * 500 = 100000
#define WUNITS (64 * 20)   // 16B units per prepped W (stride 20/row for bank-safety)
#define AP_SPAN 32         // nodes per warp in fused agg2+pool

// ---------------- scratch (static device arrays; no allocation) ----------------
__device__ int    g_deg[NN];
__device__ int    g_cur[NN];      // seeded with rowptr slot bases by k_rowptr
__device__ int    g_rowptr[NN + 1];
__device__ float  g_dinv[NN];
__device__ int    g_srcs[NE];
__device__ __half g_h16a[NN * DD];   // transform1 outputs (dinv folded), gathered
__device__ __half g_h16b[NN * DD];   // P = dinv * relu(layer1)  (agg2 input)
__device__ double g_pool[NGR * DD];
__device__ int    g_pcnt[NGR];
__device__ int    g_bsum[256];
__device__ int    g_is64;
__device__ uint4  g_wfrag[WUNITS];   // fragment-ready split-precision W1

__device__ __forceinline__ int load_idx(const void* p, long long i, int is64) {
    return is64 ? (int)((const long long*)p)[i] : ((const int*)p)[i];
}

__device__ __forceinline__ unsigned packh2(__half a, __half b) {
    __half2 t = __halves2half2(a, b);
    return *(unsigned*)&t;
}

// ---------------- launch 0: dtype detect + init + W1 fragment prep ---------------
// Fragment layout: unit(n,ks,q) = n*20 + ks*4 + q (16B each), holding
// {hi[k0],hi[k0+1],hi[k0+8],hi[k0+9], lo[...same...]} with k0 = 16*ks + 2*q,
// where hi=fp16(W[k][n]), lo=fp16(W[k][n]-hi)  (split precision, 2 MMAs).
__global__ void k_detect_init(const unsigned int* __restrict__ w,
                              const float* __restrict__ W1) {
    int i = blockIdx.x * blockDim.x + threadIdx.x;
    if (i < NN) g_deg[i] = 0;
    if (i < NGR * DD) g_pool[i] = 0.0;
    if (i < NGR) g_pcnt[i] = 0;
    if (i == 0) g_rowptr[NN] = NE;
    if (blockIdx.x == 0) {
        // int64 values < 2^31 have zero high (odd) words; int32 data won't.
        // reads first 32 KB of edge_index, in-bounds for both layouts.
        __shared__ unsigned int s;
        if (threadIdx.x == 0) s = 0u;
        __syncthreads();
        unsigned int o = 0u;
        for (int j = 1 + 2 * threadIdx.x; j < 8192; j += 2 * blockDim.x) o |= w[j];
        atomicOr(&s, o);
        __syncthreads();
        if (threadIdx.x == 0) g_is64 = (s == 0u) ? 1 : 0;
    } else if (blockIdx.x == 1) {
        for (int f = threadIdx.x; f < 1024; f += blockDim.x) {
            int n = f >> 4;
            int ks = (f >> 2) & 3;
            int q = f & 3;
            int k0 = ks * 16 + q * 2;
            float w0 = W1[(k0 + 0) * 64 + n];
            float w1 = W1[(k0 + 1) * 64 + n];
            float w8 = W1[(k0 + 8) * 64 + n];
            float w9 = W1[(k0 + 9) * 64 + n];
            __half h0 = __float2half(w0), h1 = __float2half(w1);
            __half h8 = __float2half(w8), h9 = __float2half(w9);
            uint4 v;
            v.x = packh2(h0, h1);
            v.y = packh2(h8, h9);
            v.z = packh2(__float2half(w0 - __half2float(h0)),
                         __float2half(w1 - __half2float(h1)));
            v.w = packh2(__float2half(w8 - __half2float(h8)),
                         __float2half(w9 - __half2float(h9)));
            g_wfrag[n * 20 + ks * 4 + q] = v;
        }
    }
}

// ---------------- launch 1: degree histogram over dst (2 edges/thread) -----------
__global__ void k_hist(const void* __restrict__ ei) {
    int t = blockIdx.x * blockDim.x + threadIdx.x;
    if (t * 2 >= NE) return;
    if (g_is64) {
        const longlong2* d = (const longlong2*)((const long long*)ei + NE);
        longlong2 v = d[t];
        atomicAdd(&g_deg[(int)v.x], 1);
        atomicAdd(&g_deg[(int)v.y], 1);
    } else {
        const int2* d = (const int2*)((const int*)ei + NE);
        int2 v = d[t];
        atomicAdd(&g_deg[v.x], 1);
        atomicAdd(&g_deg[v.y], 1);
    }
}

// ---------------- launch 2: per-chunk sums + dinv --------------------------------
__global__ void k_bsum_dinv() {
    __shared__ int ssum[256];
    int b = blockIdx.x;
    int base = b * SCAN_CH;
    int s = 0;
    for (int j = threadIdx.x; j < SCAN_CH; j += 256) {
        int idx = base + j;
        if (idx < NN) {
            int d = g_deg[idx];
            s += d;
            g_dinv[idx] = rsqrtf((float)(d + 1));
        }
    }
    ssum[threadIdx.x] = s;
    __syncthreads();
    for (int o = 128; o > 0; o >>= 1) {
        if (threadIdx.x < o) ssum[threadIdx.x] += ssum[threadIdx.x + o];
        __syncthreads();
    }
    if (threadIdx.x == 0) g_bsum[b] = ssum[0];
}

// ---------------- launch 3: tensor-core transform1 (2 tiles per block) -----------
// out = fp16( (in @ W1) * dinv ). Two 128x64 tiles per block (256 thr, 8 warps);
// sW loaded once. B fragments: one LDS.128 = {bh0,bh1,bl0,bl1} (split precision).
__device__ __forceinline__ void mma16816(float* c, unsigned a0, unsigned a1,
                                         unsigned a2, unsigned a3,
                                         unsigned b0, unsigned b1) {
    asm volatile(
        "mma.sync.aligned.m16n8k16.row.col.f32.f16.f16.f32 "
        "{%0,%1,%2,%3}, {%4,%5,%6,%7}, {%8,%9}, {%0,%1,%2,%3};\n"
        : "+f"(c[0]), "+f"(c[1]), "+f"(c[2]), "+f"(c[3])
        : "r"(a0), "r"(a1), "r"(a2), "r"(a3), "r"(b0), "r"(b1));
}

__global__ void __launch_bounds__(256) k_transform(const float* __restrict__ in,
                                                   __half* __restrict__ out) {
    __shared__ __align__(16) __half sA[128][72];  // x tile, fp16, padded
    __shared__ uint4 sW[WUNITS];                  // prepped W fragments

    int tid = threadIdx.x;

    // W fragments -> shared once (vectorized 16B copies)
    for (int i = tid; i < WUNITS; i += 256) sW[i] = g_wfrag[i];

    int warp = tid >> 5, lane = tid & 31;
    int g4 = lane >> 2;  // 0..7
    int q = lane & 3;
    int rbase = warp * 16;

#pragma unroll
    for (int tile = 0; tile < 2; tile++) {
        int row0 = blockIdx.x * 256 + tile * 128;
        if (row0 >= NN) break;

        // x tile -> shared fp16 (vectorized; zero-pad rows >= NN)
        const float4* xin = (const float4*)((const void*)(in + (size_t)row0 * 64));
        for (int i = tid; i < 2048; i += 256) {
            int r = i >> 4, c4 = i & 15;
            int rr = row0 + r;
            float4 v = (rr < NN) ? xin[i] : make_float4(0.f, 0.f, 0.f, 0.f);
            uint2 s2;
            s2.x = packh2(__float2half(v.x), __float2half(v.y));
            s2.y = packh2(__float2half(v.z), __float2half(v.w));
            *(uint2*)&sA[r][c4 * 4] = s2;
        }
        __syncthreads();

        float c[8][4];
#pragma unroll
        for (int g = 0; g < 8; g++) {
            c[g][0] = 0.f; c[g][1] = 0.f; c[g][2] = 0.f; c[g][3] = 0.f;
        }

#pragma unroll
        for (int ks = 0; ks < 4; ks++) {
            int k0 = ks * 16;
            unsigned a0 = *(const unsigned*)&sA[rbase + g4][k0 + q * 2];
            unsigned a1 = *(const unsigned*)&sA[rbase + g4 + 8][k0 + q * 2];
            unsigned a2 = *(const unsigned*)&sA[rbase + g4][k0 + q * 2 + 8];
            unsigned a3 = *(const unsigned*)&sA[rbase + g4 + 8][k0 + q * 2 + 8];
#pragma unroll
            for (int g = 0; g < 8; g++) {
                int n = g * 8 + g4;
                uint4 bb = sW[n * 20 + ks * 4 + q];   // {bh0,bh1,bl0,bl1}
                mma16816(c[g], a0, a1, a2, a3, bb.x, bb.y);
                mma16816(c[g], a0, a1, a2, a3, bb.z, bb.w);
            }
        }
        __syncthreads();  // all warps done reading sA before next tile's fill

        // epilogue: scale by dinv[row], fp16 store
        int r0 = row0 + rbase + g4;
        int r1 = r0 + 8;
        float dv0 = (r0 < NN) ? g_dinv[r0] : 0.f;
        float dv1 = (r1 < NN) ? g_dinv[r1] : 0.f;
#pragma unroll
        for (int g = 0; g < 8; g++) {
            int col = g * 8 + q * 2;
            if (r0 < NN)
                *(__half2*)&out[r0 * 64 + col] =
                    __floats2half2_rn(c[g][0] * dv0, c[g][1] * dv0);
            if (r1 < NN)
                *(__half2*)&out[r1 * 64 + col] =
                    __floats2half2_rn(c[g][2] * dv1, c[g][3] * dv1);
        }
    }
}

// ---------------- side branch: row_ptr (+ seed g_cur); inlines the chunk scan ----
__global__ void __launch_bounds__(256) k_rowptr() {
    __shared__ int sb_[256];
    __shared__ int sh[256];
    int t = threadIdx.x, b = blockIdx.x;
    int v = (t < SCAN_NB) ? g_bsum[t] : 0;
    sb_[t] = v;
    __syncthreads();
    for (int o = 1; o < 256; o <<= 1) {
        int xv = sb_[t];
        int yv = (t >= o) ? sb_[t - o] : 0;
        __syncthreads();
        sb_[t] = xv + yv;
        __syncthreads();
    }
    int chunk_off = (b > 0) ? sb_[b - 1] : 0;

    int base = b * SCAN_CH;
    int i0 = base + t * 4;
    int d0 = 0, d1 = 0, d2 = 0, d3 = 0;
    if (t < 125) {  // 125*4 = 500
        d0 = g_deg[i0 + 0];
        d1 = g_deg[i0 + 1];
        d2 = g_deg[i0 + 2];
        d3 = g_deg[i0 + 3];
    }
    int s = d0 + d1 + d2 + d3;
    sh[t] = s;
    __syncthreads();
    for (int o = 1; o < 256; o <<= 1) {
        int xv = sh[t];
        int yv = (t >= o) ? sh[t - o] : 0;
        __syncthreads();
        sh[t] = xv + yv;
        __syncthreads();
    }
    int excl = sh[t] - s + chunk_off;
    if (t < 125) {
        g_rowptr[i0 + 0] = excl;                g_cur[i0 + 0] = excl;
        g_rowptr[i0 + 1] = excl + d0;           g_cur[i0 + 1] = excl + d0;
        g_rowptr[i0 + 2] = excl + d0 + d1;      g_cur[i0 + 2] = excl + d0 + d1;
        g_rowptr[i0 + 3] = excl + d0 + d1 + d2; g_cur[i0 + 3] = excl + d0 + d1 + d2;
    }
}

// ---------------- side branch: scatter edges into CSR slots (2 edges/thread) -----
__global__ void k_scatter(const void* __restrict__ ei) {
    int t = blockIdx.x * blockDim.x + threadIdx.x;
    if (t * 2 >= NE) return;
    if (g_is64) {
        const longlong2* sp = (const longlong2*)ei;
        const longlong2* dp = (const longlong2*)((const long long*)ei + NE);
        longlong2 sv = sp[t];
        longlong2 dv = dp[t];
        int slot0 = atomicAdd(&g_cur[(int)dv.x], 1);
        g_srcs[slot0] = (int)sv.x;
        int slot1 = atomicAdd(&g_cur[(int)dv.y], 1);
        g_srcs[slot1] = (int)sv.y;
    } else {
        const int2* sp = (const int2*)ei;
        const int2* dp = (const int2*)((const int*)ei + NE);
        int2 sv = sp[t];
        int2 dv = dp[t];
        int slot0 = atomicAdd(&g_cur[dv.x], 1);
        g_srcs[slot0] = sv.x;
        int slot1 = atomicAdd(&g_cur[dv.y], 1);
        g_srcs[slot1] = sv.y;
    }
}

// ---------------- CSR gather for one node (warp-wide, lane = 2 feature pairs) ----
__device__ __forceinline__ float2 gather_node(const __half2* __restrict__ hp,
                                              int node, int lane) {
    float2 a0 = __half22float2(hp[node * 32 + lane]);  // self-loop term
    float2 a1 = make_float2(0.f, 0.f);
    float2 a2 = make_float2(0.f, 0.f);
    float2 a3 = make_float2(0.f, 0.f);
    int beg = g_rowptr[node];
    int end = g_rowptr[node + 1];
    int i = beg;
    for (; i + 8 <= end; i += 8) {
        int s0 = g_srcs[i + 0], s1 = g_srcs[i + 1];
        int s2 = g_srcs[i + 2], s3 = g_srcs[i + 3];
        int s4 = g_srcs[i + 4], s5 = g_srcs[i + 5];
        int s6 = g_srcs[i + 6], s7 = g_srcs[i + 7];
        float2 v0 = __half22float2(hp[s0 * 32 + lane]);
        float2 v1 = __half22float2(hp[s1 * 32 + lane]);
        float2 v2 = __half22float2(hp[s2 * 32 + lane]);
        float2 v3 = __half22float2(hp[s3 * 32 + lane]);
        float2 v4 = __half22float2(hp[s4 * 32 + lane]);
        float2 v5 = __half22float2(hp[s5 * 32 + lane]);
        float2 v6 = __half22float2(hp[s6 * 32 + lane]);
        float2 v7 = __half22float2(hp[s7 * 32 + lane]);
        a0.x += v0.x; a0.y += v0.y;  a1.x += v1.x; a1.y += v1.y;
        a2.x += v2.x; a2.y += v2.y;  a3.x += v3.x; a3.y += v3.y;
        a0.x += v4.x; a0.y += v4.y;  a1.x += v5.x; a1.y += v5.y;
        a2.x += v6.x; a2.y += v6.y;  a3.x += v7.x; a3.y += v7.y;
    }
    for (; i + 2 <= end; i += 2) {
        int s0 = g_srcs[i + 0], s1 = g_srcs[i + 1];
        float2 v0 = __half22float2(hp[s0 * 32 + lane]);
        float2 v1 = __half22float2(hp[s1 * 32 + lane]);
        a0.x += v0.x; a0.y += v0.y;
        a1.x += v1.x; a1.y += v1.y;
    }
    if (i < end) {
        int s = g_srcs[i];
        float2 v = __half22float2(hp[s * 32 + lane]);
        a2.x += v.x; a2.y += v.y;
    }
    return make_float2((a0.x + a1.x) + (a2.x + a3.x),
                       (a0.y + a1.y) + (a2.y + a3.y));
}

// ---------------- agg1 — warp per dst node ---------------------------------------
// P_d = fp16( dinv_d * relu(dinv_d * acc + b1) )   (next layer's source scaling folded)
__global__ void __launch_bounds__(256) k_agg1(const __half2* __restrict__ hp,
                                              const float* __restrict__ bias,
                                              __half2* __restrict__ outp) {
    int gw = (blockIdx.x * blockDim.x + threadIdx.x) >> 5;
    if (gw >= NN) return;
    int lane = threadIdx.x & 31;
    float2 acc = gather_node(hp, gw, lane);
    float dv = g_dinv[gw];
    float ox = fmaxf(acc.x * dv + bias[lane * 2 + 0], 0.f) * dv;
    float oy = fmaxf(acc.y * dv + bias[lane * 2 + 1], 0.f) * dv;
    outp[gw * 32 + lane] = __float22half2_rn(make_float2(ox, oy));
}

// ---------------- fused agg2 + pool ----------------------------------------------
// Warp handles AP_SPAN contiguous nodes (batch sorted): z_d = dinv_d * acc_d is
// accumulated into per-lane registers, flushed to g_pool on graph boundaries.
__global__ void __launch_bounds__(256) k_aggpool(const __half2* __restrict__ hp,
                                                 const void* __restrict__ batch) {
    int gw = (blockIdx.x * blockDim.x + threadIdx.x) >> 5;
    int lane = threadIdx.x & 31;
    int n0 = gw * AP_SPAN;
    if (n0 >= NN) return;
    int n1 = n0 + AP_SPAN;
    if (n1 > NN) n1 = NN;
    int is64 = g_is64;

    int g = load_idx(batch, n0, is64);
    float sx = 0.f, sy = 0.f;
    int cnt = 0;
    for (int node = n0; node < n1; node++) {
        int gn = load_idx(batch, node, is64);
        if (gn != g) {
            atomicAdd(&g_pool[g * DD + lane * 2 + 0], (double)sx);
            atomicAdd(&g_pool[g * DD + lane * 2 + 1], (double)sy);
            if (lane == 0) atomicAdd(&g_pcnt[g], cnt);
            sx = 0.f; sy = 0.f; cnt = 0; g = gn;
        }
        float2 acc = gather_node(hp, node, lane);
        float dv = g_dinv[node];
        sx += acc.x * dv;
        sy += acc.y * dv;
        cnt++;
    }
    atomicAdd(&g_pool[g * DD + lane * 2 + 0], (double)sx);
    atomicAdd(&g_pool[g * DD + lane * 2 + 1], (double)sy);
    if (lane == 0) atomicAdd(&g_pcnt[g], cnt);
}

// ---------------- finalize = (pooled mean) @ W2 + b2  (fp32) ---------------------
__global__ void k_final(const float* __restrict__ W2,
                        const float* __restrict__ b2,
                        float* __restrict__ out) {
    __shared__ float sm[NGR][DD];
    int t = threadIdx.x;            // 1024 = 16*64
    int g = t >> 6, n = t & 63;
    int c = g_pcnt[g];
    double denom = (double)(c > 1 ? c : 1);
    sm[g][n] = (float)(g_pool[g * DD + n] / denom);
    __syncthreads();
    float acc = 0.f;
#pragma unroll
    for (int k = 0; k < DD; k++) acc = fmaf(sm[g][k], W2[k * DD + n], acc);
    out[t] = acc + b2[n];
}

// ---------------- launch ----------------
extern "C" void kernel_launch(void* const* d_in, const int* in_sizes, int n_in,
                              void* d_out, int out_size) {
    const float* x  = (const float*)d_in[0];
    const float* W1 = (const float*)d_in[1];
    const float* b1 = (const float*)d_in[2];
    const float* W2 = (const float*)d_in[3];
    const float* b2 = (const float*)d_in[4];
    const void*  ei = d_in[5];      // (2, NE) row-major, int32 OR int64 (detected)
    const void*  batch = d_in[6];
    float* out = (float*)d_out;

    __half* h16a; cudaGetSymbolAddress((void**)&h16a, g_h16a);
    __half* h16b; cudaGetSymbolAddress((void**)&h16b, g_h16b);

    int tgrid = (NN + 255) / 256;                // 391 blocks, 2 tiles each
    int apwarps = (NN + AP_SPAN - 1) / AP_SPAN;  // 3125 warps

    // fork/join events (no device memory; kernel_launch is called only twice per
    // run — correctness + capture — so not destroying them is a bounded leak)
    cudaEvent_t ev_fork, ev_join;
    cudaEventCreateWithFlags(&ev_fork, cudaEventDisableTiming);
    cudaEventCreateWithFlags(&ev_join, cudaEventDisableTiming);
    cudaStream_t side = cudaStreamPerThread;     // no creation needed

    k_detect_init<<<(NN + 255) / 256, 256>>>((const unsigned int*)ei, W1);   // 0
    k_hist<<<(NE / 2 + 255) / 256, 256>>>(ei);                               // 1
    k_bsum_dinv<<<SCAN_NB, 256>>>();                                         // 2

    // fork: CSR build on side stream, transform on origin stream (parallel branches)
    cudaEventRecord(ev_fork, 0);
    cudaStreamWaitEvent(side, ev_fork, 0);

    k_transform<<<tgrid, 256>>>(x, h16a);                                    // 3 (profiled)
    k_rowptr<<<SCAN_NB, 256, 0, side>>>();
    k_scatter<<<(NE / 2 + 255) / 256, 256, 0, side>>>(ei);

    // join: agg1 needs both transform (origin, program order) and scatter (event)
    cudaEventRecord(ev_join, side);
    cudaStreamWaitEvent(0, ev_join, 0);

    k_agg1<<<(NN * 32 + 255) / 256, 256>>>((const __half2*)h16a, b1,
                                           (__half2*)h16b);
    k_aggpool<<<(apwarps * 32 + 255) / 256, 256>>>((const __half2*)h16b, batch);
    k_final<<<1, 1024>>>(W2, b2, out);
}